// round 10
// baseline (speedup 1.0000x reference)
#include <cuda_runtime.h>
#include <cstdint>

// Problem constants
#define TT 4096      // B*S tokens
#define HH 1024      // hidden
#define II 2048      // intermediate
#define EE 8         // experts

#define AKP 20       // A smem row stride (16 + 4 pad) words -> conflict-free frag LDS
#define BNP 136      // B smem row stride (128 + 8 pad) words -> conflict-free frag LDS
#define NSTAGE 3

// ---------------- scratch (device globals: no allocation allowed) ----------
__device__ float g_F[(size_t)2 * TT * II];      // fused activations, tf32-pre-rounded (64 MB)
__device__ float g_slot[(size_t)2 * TT * HH];   // per-(token,k) outputs (32 MB)
__device__ int   g_cnt[EE];
__device__ int   g_rows[EE * TT];               // stores r = t*2 + k
__device__ float g_wts[EE * TT];

// ---------------- helpers ----------------
__device__ __forceinline__ unsigned f2tf(float f) {
    unsigned u;
    asm("cvt.rna.tf32.f32 %0, %1;" : "=r"(u) : "f"(f));
    return u;
}

__device__ __forceinline__ void cp16(float* smem_dst, const float* gmem_src) {
    unsigned s = (unsigned)__cvta_generic_to_shared(smem_dst);
    asm volatile("cp.async.cg.shared.global [%0], [%1], 16;\n" :: "r"(s), "l"(gmem_src));
}
#define CP_COMMIT() asm volatile("cp.async.commit_group;\n" ::: "memory")
#define CP_WAIT2()  asm volatile("cp.async.wait_group 2;\n" ::: "memory")

__device__ __forceinline__ void mma_tf32(float c[4], const unsigned a[4], const unsigned b[2]) {
    asm volatile(
        "mma.sync.aligned.m16n8k8.row.col.f32.tf32.tf32.f32 "
        "{%0,%1,%2,%3}, {%4,%5,%6,%7}, {%8,%9}, {%0,%1,%2,%3};\n"
        : "+f"(c[0]), "+f"(c[1]), "+f"(c[2]), "+f"(c[3])
        : "r"(a[0]), "r"(a[1]), "r"(a[2]), "r"(a[3]), "r"(b[0]), "r"(b[1]));
}

// ---------------- 0: zero expert counters ----------------
__global__ void zero_cnt_kernel() {
    if (threadIdx.x < EE) g_cnt[threadIdx.x] = 0;
}

// ---------------- 1: router (1 warp per token) ----------------
__global__ void router_kernel(const float* __restrict__ x, const float* __restrict__ Wg) {
    int t = (blockIdx.x * blockDim.x + threadIdx.x) >> 5;
    int lane = threadIdx.x & 31;
    if (t >= TT) return;
    const float* xr = x + (size_t)t * HH;
    float acc[EE];
#pragma unroll
    for (int e = 0; e < EE; e++) acc[e] = 0.f;
    for (int h = lane; h < HH; h += 32) {
        float xv = xr[h];
        const float4* wg = reinterpret_cast<const float4*>(Wg + h * EE);
        float4 w0 = wg[0], w1 = wg[1];
        acc[0] += xv * w0.x; acc[1] += xv * w0.y; acc[2] += xv * w0.z; acc[3] += xv * w0.w;
        acc[4] += xv * w1.x; acc[5] += xv * w1.y; acc[6] += xv * w1.z; acc[7] += xv * w1.w;
    }
#pragma unroll
    for (int off = 16; off > 0; off >>= 1) {
#pragma unroll
        for (int e = 0; e < EE; e++)
            acc[e] += __shfl_xor_sync(0xffffffffu, acc[e], off);
    }
    if (lane == 0) {
        float m = acc[0];
#pragma unroll
        for (int e = 1; e < EE; e++) m = fmaxf(m, acc[e]);
        float p[EE];
        float s = 0.f;
#pragma unroll
        for (int e = 0; e < EE; e++) { p[e] = __expf(acc[e] - m); s += p[e]; }
        float inv = 1.f / s;
        int i0 = 0;
#pragma unroll
        for (int e = 1; e < EE; e++) if (p[e] > p[i0]) i0 = e;
        int i1 = -1;
#pragma unroll
        for (int e = 0; e < EE; e++) {
            if (e == i0) continue;
            if (i1 < 0 || p[e] > p[i1]) i1 = e;
        }
        float s0 = p[i0] * inv, s1 = p[i1] * inv;
        float denom = s0 + s1 + 1e-8f;
        float w0 = s0 / denom, w1 = s1 / denom;
        int pos0 = atomicAdd(&g_cnt[i0], 1);
        g_rows[i0 * TT + pos0] = t * 2 + 0;
        g_wts[i0 * TT + pos0] = w0;
        int pos1 = atomicAdd(&g_cnt[i1], 1);
        g_rows[i1 * TT + pos1] = t * 2 + 1;
        g_wts[i1 * TT + pos1] = w1;
    }
}

// dynamic smem sizes
#define G1_A_WORDS   (64 * AKP)
#define G1_B_WORDS   (16 * BNP)
#define G1_SMEM_B    ((NSTAGE * (G1_A_WORDS + 2 * G1_B_WORDS)) * 4)
#define G2_A_WORDS   (128 * AKP)
#define G2_B_WORDS   (16 * BNP)
#define G2_SMEM_B    ((NSTAGE * (G2_A_WORDS + G2_B_WORDS)) * 4)

// ---------------- 2: grouped GEMM1: F = SiLU(X@W11) * (X@W12) ----------------
// 256 threads. BM=64, BN=128, BK=16, 3-stage cp.async ring.
// Warps 2(m) x 4(n); warp tile 32x32, dual accumulators (G and V).
// grid: (II/128, TT/64, EE)
__global__ __launch_bounds__(256, 2) void gemm1_kernel(
    const float* __restrict__ x,
    const float* __restrict__ W11,
    const float* __restrict__ W12)
{
    extern __shared__ float dyn[];
    int e = blockIdx.z;
    int cnt = g_cnt[e];
    int m0 = blockIdx.y * 64;
    if (m0 >= cnt) return;
    int n0 = blockIdx.x * 128;

    float* AsB  = dyn;                                   // [NSTAGE][64][AKP]
    float* B1sB = dyn + NSTAGE * G1_A_WORDS;             // [NSTAGE][16][BNP]
    float* B2sB = B1sB + NSTAGE * G1_B_WORDS;            // [NSTAGE][16][BNP]
    __shared__ int rloc[64];

    int tid = threadIdx.x;
    int lane = tid & 31;
    int warp = tid >> 5;
    int wm = (warp >> 2) * 32;     // 0 or 32
    int wn = (warp & 3) * 32;      // 0,32,64,96

    if (tid < 64) {
        int mi = m0 + tid;
        if (mi >= cnt) mi = cnt - 1;
        rloc[tid] = g_rows[e * TT + mi];
    }
    __syncthreads();

    const float* W11base = W11 + (size_t)e * HH * II + n0;
    const float* W12base = W12 + (size_t)e * HH * II + n0;

    // per-thread staging coordinates
    int a_row = tid >> 2, a_cg = (tid & 3) * 4;
    int b_kr0 = tid >> 5, b_cg = (tid & 31) * 4;
    const float* a_src = x + (size_t)(rloc[a_row] >> 1) * HH + a_cg;

    float cG[2][4][4], cV[2][4][4];
#pragma unroll
    for (int a = 0; a < 2; a++)
#pragma unroll
        for (int b = 0; b < 4; b++)
#pragma unroll
            for (int c = 0; c < 4; c++) { cG[a][b][c] = 0.f; cV[a][b][c] = 0.f; }

    const int NIT = HH / 16;

    // prologue: prefetch tiles 0 and 1 (one commit group each)
#pragma unroll
    for (int pre = 0; pre < 2; pre++) {
        int kk = pre * 16;
        float* As = AsB + pre * G1_A_WORDS;
        float* B1 = B1sB + pre * G1_B_WORDS;
        float* B2 = B2sB + pre * G1_B_WORDS;
        cp16(As + a_row * AKP + a_cg, a_src + kk);
#pragma unroll
        for (int p = 0; p < 2; p++) {
            int kr = b_kr0 + p * 8;
            cp16(B1 + kr * BNP + b_cg, W11base + (size_t)(kk + kr) * II + b_cg);
            cp16(B2 + kr * BNP + b_cg, W12base + (size_t)(kk + kr) * II + b_cg);
        }
        CP_COMMIT();
    }

    int buf = 0;
    for (int it = 0; it < NIT; it++) {
        if (it + 2 < NIT) {
            int kk = (it + 2) * 16;
            int s = (it + 2) % NSTAGE;
            float* As = AsB + s * G1_A_WORDS;
            float* B1 = B1sB + s * G1_B_WORDS;
            float* B2 = B2sB + s * G1_B_WORDS;
            cp16(As + a_row * AKP + a_cg, a_src + kk);
#pragma unroll
            for (int p = 0; p < 2; p++) {
                int kr = b_kr0 + p * 8;
                cp16(B1 + kr * BNP + b_cg, W11base + (size_t)(kk + kr) * II + b_cg);
                cp16(B2 + kr * BNP + b_cg, W12base + (size_t)(kk + kr) * II + b_cg);
            }
        }
        CP_COMMIT();          // one group per iteration (possibly empty at tail)
        CP_WAIT2();           // tile `it`'s group complete
        __syncthreads();

        const float* As = AsB + buf * G1_A_WORDS;
        const float* B1 = B1sB + buf * G1_B_WORDS;
        const float* B2 = B2sB + buf * G1_B_WORDS;

#pragma unroll
        for (int ks = 0; ks < 16; ks += 8) {
            unsigned a[2][4];
#pragma unroll
            for (int mt = 0; mt < 2; mt++) {
                int r = wm + mt * 16 + (lane >> 2);
                int cc = ks + (lane & 3);
                a[mt][0] = f2tf(As[r * AKP + cc]);
                a[mt][1] = f2tf(As[(r + 8) * AKP + cc]);
                a[mt][2] = f2tf(As[r * AKP + cc + 4]);
                a[mt][3] = f2tf(As[(r + 8) * AKP + cc + 4]);
            }
#pragma unroll
            for (int nt = 0; nt < 4; nt++) {
                int nc = wn + nt * 8 + (lane >> 2);
                int kr = ks + (lane & 3);
                unsigned b1[2] = { f2tf(B1[kr * BNP + nc]), f2tf(B1[(kr + 4) * BNP + nc]) };
                unsigned b2[2] = { f2tf(B2[kr * BNP + nc]), f2tf(B2[(kr + 4) * BNP + nc]) };
#pragma unroll
                for (int mt = 0; mt < 2; mt++) {
                    mma_tf32(cG[mt][nt], a[mt], b1);
                    mma_tf32(cV[mt][nt], a[mt], b2);
                }
            }
        }
        __syncthreads();
        buf++; if (buf == NSTAGE) buf = 0;
    }

    // epilogue: f = g * sigmoid(g) * v -> g_F[r], stored tf32-rounded so
    // gemm2's A fragments need no conversion.
#pragma unroll
    for (int mt = 0; mt < 2; mt++) {
#pragma unroll
        for (int half = 0; half < 2; half++) {
            int r = wm + mt * 16 + (lane >> 2) + half * 8;
            if (m0 + r < cnt) {
                int rg = rloc[r];
                float* dst = g_F + (size_t)rg * II + n0 + wn;
#pragma unroll
                for (int nt = 0; nt < 4; nt++) {
                    float g0 = cG[mt][nt][half * 2 + 0], g1 = cG[mt][nt][half * 2 + 1];
                    float v0 = cV[mt][nt][half * 2 + 0], v1 = cV[mt][nt][half * 2 + 1];
                    float f0 = g0 * v0 / (1.f + __expf(-g0));
                    float f1 = g1 * v1 / (1.f + __expf(-g1));
                    *reinterpret_cast<float2*>(dst + nt * 8 + (lane & 3) * 2) =
                        make_float2(__uint_as_float(f2tf(f0)), __uint_as_float(f2tf(f1)));
                }
            }
        }
    }
}

// ---------------- 3: grouped GEMM2: O[r] = w[r] * (F[r] @ W2[e]) ----------------
// 256 threads. BM=128, BN=128, BK=16, 3-stage cp.async ring.
// Warps 2(m) x 4(n); warp tile 64x32. A (g_F) pre-rounded -> no cvt.
// grid: (HH/128, TT/128, EE)
__global__ __launch_bounds__(256, 2) void gemm2_kernel(const float* __restrict__ W2)
{
    extern __shared__ float dyn[];
    int e = blockIdx.z;
    int cnt = g_cnt[e];
    int m0 = blockIdx.y * 128;
    if (m0 >= cnt) return;
    int n0 = blockIdx.x * 128;

    float* AsB = dyn;                                    // [NSTAGE][128][AKP]
    float* BsB = dyn + NSTAGE * G2_A_WORDS;              // [NSTAGE][16][BNP]
    __shared__ int rloc[128];
    __shared__ float wloc[128];

    int tid = threadIdx.x;
    int lane = tid & 31;
    int warp = tid >> 5;
    int wm = (warp >> 2) * 64;     // 0 or 64
    int wn = (warp & 3) * 32;      // 0,32,64,96

    if (tid < 128) {
        int mi = m0 + tid;
        if (mi >= cnt) mi = cnt - 1;
        rloc[tid] = g_rows[e * TT + mi];
        wloc[tid] = g_wts[e * TT + mi];
    }
    __syncthreads();

    const float* Bbase = W2 + (size_t)e * II * HH + n0;

    int a_row0 = tid >> 2, a_cg = (tid & 3) * 4;
    int b_kr0 = tid >> 5, b_cg = (tid & 31) * 4;
    const float* a_src0 = g_F + (size_t)rloc[a_row0] * II + a_cg;
    const float* a_src1 = g_F + (size_t)rloc[a_row0 + 64] * II + a_cg;

    float c[4][4][4];
#pragma unroll
    for (int a = 0; a < 4; a++)
#pragma unroll
        for (int b = 0; b < 4; b++)
#pragma unroll
            for (int cc = 0; cc < 4; cc++) c[a][b][cc] = 0.f;

    const int NIT = II / 16;

#pragma unroll
    for (int pre = 0; pre < 2; pre++) {
        int kk = pre * 16;
        float* As = AsB + pre * G2_A_WORDS;
        float* Bs = BsB + pre * G2_B_WORDS;
        cp16(As + a_row0 * AKP + a_cg, a_src0 + kk);
        cp16(As + (a_row0 + 64) * AKP + a_cg, a_src1 + kk);
#pragma unroll
        for (int p = 0; p < 2; p++) {
            int kr = b_kr0 + p * 8;
            cp16(Bs + kr * BNP + b_cg, Bbase + (size_t)(kk + kr) * HH + b_cg);
        }
        CP_COMMIT();
    }

    int buf = 0;
    for (int it = 0; it < NIT; it++) {
        if (it + 2 < NIT) {
            int kk = (it + 2) * 16;
            int s = (it + 2) % NSTAGE;
            float* As = AsB + s * G2_A_WORDS;
            float* Bs = BsB + s * G2_B_WORDS;
            cp16(As + a_row0 * AKP + a_cg, a_src0 + kk);
            cp16(As + (a_row0 + 64) * AKP + a_cg, a_src1 + kk);
#pragma unroll
            for (int p = 0; p < 2; p++) {
                int kr = b_kr0 + p * 8;
                cp16(Bs + kr * BNP + b_cg, Bbase + (size_t)(kk + kr) * HH + b_cg);
            }
        }
        CP_COMMIT();
        CP_WAIT2();
        __syncthreads();

        const float* As = AsB + buf * G2_A_WORDS;
        const float* Bs = BsB + buf * G2_B_WORDS;

#pragma unroll
        for (int ks = 0; ks < 16; ks += 8) {
            unsigned a[4][4];
#pragma unroll
            for (int mt = 0; mt < 4; mt++) {
                int r = wm + mt * 16 + (lane >> 2);
                int cc = ks + (lane & 3);
                a[mt][0] = __float_as_uint(As[r * AKP + cc]);
                a[mt][1] = __float_as_uint(As[(r + 8) * AKP + cc]);
                a[mt][2] = __float_as_uint(As[r * AKP + cc + 4]);
                a[mt][3] = __float_as_uint(As[(r + 8) * AKP + cc + 4]);
            }
#pragma unroll
            for (int nt = 0; nt < 4; nt++) {
                int nc = wn + nt * 8 + (lane >> 2);
                int kr = ks + (lane & 3);
                unsigned b[2] = { f2tf(Bs[kr * BNP + nc]), f2tf(Bs[(kr + 4) * BNP + nc]) };
#pragma unroll
                for (int mt = 0; mt < 4; mt++)
                    mma_tf32(c[mt][nt], a[mt], b);
            }
        }
        __syncthreads();
        buf++; if (buf == NSTAGE) buf = 0;
    }

    // epilogue: scale by routing weight, scatter to slot buffer
#pragma unroll
    for (int mt = 0; mt < 4; mt++) {
#pragma unroll
        for (int half = 0; half < 2; half++) {
            int r = wm + mt * 16 + (lane >> 2) + half * 8;
            if (m0 + r < cnt) {
                int rg = rloc[r];
                float wr = wloc[r];
                float* dst = g_slot + (size_t)rg * HH + n0 + wn;
#pragma unroll
                for (int nt = 0; nt < 4; nt++) {
                    float o0 = wr * c[mt][nt][half * 2 + 0];
                    float o1 = wr * c[mt][nt][half * 2 + 1];
                    *reinterpret_cast<float2*>(dst + nt * 8 + (lane & 3) * 2) = make_float2(o0, o1);
                }
            }
        }
    }
}

// ---------------- 4: combine the two expert slots per token ----------------
__global__ void combine_kernel(float* __restrict__ out) {
    int i = blockIdx.x * blockDim.x + threadIdx.x;   // float4 index
    const int n4 = TT * HH / 4;
    if (i >= n4) return;
    int t = i / (HH / 4);
    int h4 = i % (HH / 4);
    float4 a = reinterpret_cast<const float4*>(g_slot + (size_t)(2 * t) * HH)[h4];
    float4 b = reinterpret_cast<const float4*>(g_slot + (size_t)(2 * t + 1) * HH)[h4];
    float4 r = make_float4(a.x + b.x, a.y + b.y, a.z + b.z, a.w + b.w);
    reinterpret_cast<float4*>(out)[i] = r;
}

// ---------------- launch ----------------
extern "C" void kernel_launch(void* const* d_in, const int* in_sizes, int n_in,
                              void* d_out, int out_size) {
    (void)in_sizes; (void)n_in; (void)out_size;
    const float* x   = (const float*)d_in[0];
    const float* Wg  = (const float*)d_in[1];
    const float* W11 = (const float*)d_in[2];
    const float* W12 = (const float*)d_in[3];
    const float* W2  = (const float*)d_in[4];
    float* out = (float*)d_out;

    // raise dynamic smem caps (idempotent; host attribute set, capture-safe)
    cudaFuncSetAttribute(gemm1_kernel, cudaFuncAttributeMaxDynamicSharedMemorySize, G1_SMEM_B);
    cudaFuncSetAttribute(gemm2_kernel, cudaFuncAttributeMaxDynamicSharedMemorySize, G2_SMEM_B);

    zero_cnt_kernel<<<1, 32>>>();
    router_kernel<<<TT / 4, 128>>>(x, Wg);                 // 4 warps/block

    dim3 g1(II / 128, TT / 64, EE);                        // (16, 64, 8)
    gemm1_kernel<<<g1, 256, G1_SMEM_B>>>(x, W11, W12);

    dim3 g2(HH / 128, TT / 128, EE);                       // (8, 32, 8)
    gemm2_kernel<<<g2, 256, G2_SMEM_B>>>(W2);

    combine_kernel<<<(TT * HH / 4 + 255) / 256, 256>>>(out);
}

// round 11
// speedup vs baseline: 1.0653x; 1.0653x over previous
#include <cuda_runtime.h>
#include <cstdint>

// Problem constants
#define TT 4096      // B*S tokens
#define HH 1024      // hidden
#define II 2048      // intermediate
#define EE 8         // experts

#define AKP 20       // A smem row stride (16 + 4 pad) words -> conflict-free frag LDS
#define BNP 136      // B smem row stride (128 + 8 pad) words -> conflict-free frag LDS
#define NSTAGE 4     // 4 stages + lead-2 prefetch => trailing barrier provably unnecessary

// ---------------- scratch (device globals: no allocation allowed) ----------
__device__ float g_F[(size_t)2 * TT * II];      // fused activations, tf32-pre-rounded (64 MB)
__device__ float g_slot[(size_t)2 * TT * HH];   // per-(token,k) outputs (32 MB)
__device__ int   g_cnt[EE];
__device__ int   g_rows[EE * TT];               // stores r = t*2 + k
__device__ float g_wts[EE * TT];

// ---------------- helpers ----------------
__device__ __forceinline__ unsigned f2tf(float f) {
    unsigned u;
    asm("cvt.rna.tf32.f32 %0, %1;" : "=r"(u) : "f"(f));
    return u;
}

__device__ __forceinline__ void cp16(float* smem_dst, const float* gmem_src) {
    unsigned s = (unsigned)__cvta_generic_to_shared(smem_dst);
    asm volatile("cp.async.cg.shared.global [%0], [%1], 16;\n" :: "r"(s), "l"(gmem_src));
}
#define CP_COMMIT() asm volatile("cp.async.commit_group;\n" ::: "memory")
#define CP_WAIT2()  asm volatile("cp.async.wait_group 2;\n" ::: "memory")

__device__ __forceinline__ void mma_tf32(float c[4], const unsigned a[4], const unsigned b[2]) {
    asm volatile(
        "mma.sync.aligned.m16n8k8.row.col.f32.tf32.tf32.f32 "
        "{%0,%1,%2,%3}, {%4,%5,%6,%7}, {%8,%9}, {%0,%1,%2,%3};\n"
        : "+f"(c[0]), "+f"(c[1]), "+f"(c[2]), "+f"(c[3])
        : "r"(a[0]), "r"(a[1]), "r"(a[2]), "r"(a[3]), "r"(b[0]), "r"(b[1]));
}

// ---------------- 0: zero expert counters ----------------
__global__ void zero_cnt_kernel() {
    if (threadIdx.x < EE) g_cnt[threadIdx.x] = 0;
}

// ---------------- 1: router (1 warp per token) ----------------
__global__ void router_kernel(const float* __restrict__ x, const float* __restrict__ Wg) {
    int t = (blockIdx.x * blockDim.x + threadIdx.x) >> 5;
    int lane = threadIdx.x & 31;
    if (t >= TT) return;
    const float* xr = x + (size_t)t * HH;
    float acc[EE];
#pragma unroll
    for (int e = 0; e < EE; e++) acc[e] = 0.f;
    for (int h = lane; h < HH; h += 32) {
        float xv = xr[h];
        const float4* wg = reinterpret_cast<const float4*>(Wg + h * EE);
        float4 w0 = wg[0], w1 = wg[1];
        acc[0] += xv * w0.x; acc[1] += xv * w0.y; acc[2] += xv * w0.z; acc[3] += xv * w0.w;
        acc[4] += xv * w1.x; acc[5] += xv * w1.y; acc[6] += xv * w1.z; acc[7] += xv * w1.w;
    }
#pragma unroll
    for (int off = 16; off > 0; off >>= 1) {
#pragma unroll
        for (int e = 0; e < EE; e++)
            acc[e] += __shfl_xor_sync(0xffffffffu, acc[e], off);
    }
    if (lane == 0) {
        float m = acc[0];
#pragma unroll
        for (int e = 1; e < EE; e++) m = fmaxf(m, acc[e]);
        float p[EE];
        float s = 0.f;
#pragma unroll
        for (int e = 0; e < EE; e++) { p[e] = __expf(acc[e] - m); s += p[e]; }
        float inv = 1.f / s;
        int i0 = 0;
#pragma unroll
        for (int e = 1; e < EE; e++) if (p[e] > p[i0]) i0 = e;
        int i1 = -1;
#pragma unroll
        for (int e = 0; e < EE; e++) {
            if (e == i0) continue;
            if (i1 < 0 || p[e] > p[i1]) i1 = e;
        }
        float s0 = p[i0] * inv, s1 = p[i1] * inv;
        float denom = s0 + s1 + 1e-8f;
        float w0 = s0 / denom, w1 = s1 / denom;
        int pos0 = atomicAdd(&g_cnt[i0], 1);
        g_rows[i0 * TT + pos0] = t * 2 + 0;
        g_wts[i0 * TT + pos0] = w0;
        int pos1 = atomicAdd(&g_cnt[i1], 1);
        g_rows[i1 * TT + pos1] = t * 2 + 1;
        g_wts[i1 * TT + pos1] = w1;
    }
}

// dynamic smem sizes
#define G1_A_WORDS   (64 * AKP)
#define G1_B_WORDS   (16 * BNP)
#define G1_SMEM_B    ((NSTAGE * (G1_A_WORDS + 2 * G1_B_WORDS)) * 4)
#define G2_A_WORDS   (128 * AKP)
#define G2_B_WORDS   (16 * BNP)
#define G2_SMEM_B    ((NSTAGE * (G2_A_WORDS + G2_B_WORDS)) * 4)

// ---------------- 2: grouped GEMM1: F = SiLU(X@W11) * (X@W12) ----------------
// 256 threads. BM=64, BN=128, BK=16, 4-stage cp.async ring (lead 2).
// One barrier per iteration; trailing barrier removed (safe: prefetch stage
// it+2 mod 4 never collides with compute stages {it, it-1} mod 4).
// grid: (II/128, TT/64, EE)
__global__ __launch_bounds__(256, 2) void gemm1_kernel(
    const float* __restrict__ x,
    const float* __restrict__ W11,
    const float* __restrict__ W12)
{
    extern __shared__ float dyn[];
    int e = blockIdx.z;
    int cnt = g_cnt[e];
    int m0 = blockIdx.y * 64;
    if (m0 >= cnt) return;
    int n0 = blockIdx.x * 128;

    float* AsB  = dyn;                                   // [NSTAGE][64][AKP]
    float* B1sB = dyn + NSTAGE * G1_A_WORDS;             // [NSTAGE][16][BNP]
    float* B2sB = B1sB + NSTAGE * G1_B_WORDS;            // [NSTAGE][16][BNP]
    __shared__ int rloc[64];

    int tid = threadIdx.x;
    int lane = tid & 31;
    int warp = tid >> 5;
    int wm = (warp >> 2) * 32;     // 0 or 32
    int wn = (warp & 3) * 32;      // 0,32,64,96

    if (tid < 64) {
        int mi = m0 + tid;
        if (mi >= cnt) mi = cnt - 1;
        rloc[tid] = g_rows[e * TT + mi];
    }
    __syncthreads();

    const float* W11base = W11 + (size_t)e * HH * II + n0;
    const float* W12base = W12 + (size_t)e * HH * II + n0;

    int a_row = tid >> 2, a_cg = (tid & 3) * 4;
    int b_kr0 = tid >> 5, b_cg = (tid & 31) * 4;
    const float* a_src = x + (size_t)(rloc[a_row] >> 1) * HH + a_cg;

    float cG[2][4][4], cV[2][4][4];
#pragma unroll
    for (int a = 0; a < 2; a++)
#pragma unroll
        for (int b = 0; b < 4; b++)
#pragma unroll
            for (int c = 0; c < 4; c++) { cG[a][b][c] = 0.f; cV[a][b][c] = 0.f; }

    const int NIT = HH / 16;

    // prologue: prefetch tiles 0 and 1 (one commit group each)
#pragma unroll
    for (int pre = 0; pre < 2; pre++) {
        int kk = pre * 16;
        float* As = AsB + pre * G1_A_WORDS;
        float* B1 = B1sB + pre * G1_B_WORDS;
        float* B2 = B2sB + pre * G1_B_WORDS;
        cp16(As + a_row * AKP + a_cg, a_src + kk);
#pragma unroll
        for (int p = 0; p < 2; p++) {
            int kr = b_kr0 + p * 8;
            cp16(B1 + kr * BNP + b_cg, W11base + (size_t)(kk + kr) * II + b_cg);
            cp16(B2 + kr * BNP + b_cg, W12base + (size_t)(kk + kr) * II + b_cg);
        }
        CP_COMMIT();
    }

    int buf = 0;
    for (int it = 0; it < NIT; it++) {
        if (it + 2 < NIT) {
            int kk = (it + 2) * 16;
            int s = (it + 2) & (NSTAGE - 1);
            float* As = AsB + s * G1_A_WORDS;
            float* B1 = B1sB + s * G1_B_WORDS;
            float* B2 = B2sB + s * G1_B_WORDS;
            cp16(As + a_row * AKP + a_cg, a_src + kk);
#pragma unroll
            for (int p = 0; p < 2; p++) {
                int kr = b_kr0 + p * 8;
                cp16(B1 + kr * BNP + b_cg, W11base + (size_t)(kk + kr) * II + b_cg);
                cp16(B2 + kr * BNP + b_cg, W12base + (size_t)(kk + kr) * II + b_cg);
            }
        }
        CP_COMMIT();          // one group per iteration (possibly empty at tail)
        CP_WAIT2();           // tile `it`'s group complete
        __syncthreads();      // single barrier per iteration

        const float* As = AsB + buf * G1_A_WORDS;
        const float* B1 = B1sB + buf * G1_B_WORDS;
        const float* B2 = B2sB + buf * G1_B_WORDS;

#pragma unroll
        for (int ks = 0; ks < 16; ks += 8) {
            unsigned a[2][4];
#pragma unroll
            for (int mt = 0; mt < 2; mt++) {
                int r = wm + mt * 16 + (lane >> 2);
                int cc = ks + (lane & 3);
                a[mt][0] = f2tf(As[r * AKP + cc]);
                a[mt][1] = f2tf(As[(r + 8) * AKP + cc]);
                a[mt][2] = f2tf(As[r * AKP + cc + 4]);
                a[mt][3] = f2tf(As[(r + 8) * AKP + cc + 4]);
            }
#pragma unroll
            for (int nt = 0; nt < 4; nt++) {
                int nc = wn + nt * 8 + (lane >> 2);
                int kr = ks + (lane & 3);
                unsigned b1[2] = { f2tf(B1[kr * BNP + nc]), f2tf(B1[(kr + 4) * BNP + nc]) };
                unsigned b2[2] = { f2tf(B2[kr * BNP + nc]), f2tf(B2[(kr + 4) * BNP + nc]) };
#pragma unroll
                for (int mt = 0; mt < 2; mt++) {
                    mma_tf32(cG[mt][nt], a[mt], b1);
                    mma_tf32(cV[mt][nt], a[mt], b2);
                }
            }
        }
        buf++; if (buf == NSTAGE) buf = 0;
    }

    // epilogue: f = g * sigmoid(g) * v -> g_F[r], stored tf32-rounded so
    // gemm2's A fragments need no conversion.
#pragma unroll
    for (int mt = 0; mt < 2; mt++) {
#pragma unroll
        for (int half = 0; half < 2; half++) {
            int r = wm + mt * 16 + (lane >> 2) + half * 8;
            if (m0 + r < cnt) {
                int rg = rloc[r];
                float* dst = g_F + (size_t)rg * II + n0 + wn;
#pragma unroll
                for (int nt = 0; nt < 4; nt++) {
                    float g0 = cG[mt][nt][half * 2 + 0], g1 = cG[mt][nt][half * 2 + 1];
                    float v0 = cV[mt][nt][half * 2 + 0], v1 = cV[mt][nt][half * 2 + 1];
                    float f0 = g0 * v0 / (1.f + __expf(-g0));
                    float f1 = g1 * v1 / (1.f + __expf(-g1));
                    *reinterpret_cast<float2*>(dst + nt * 8 + (lane & 3) * 2) =
                        make_float2(__uint_as_float(f2tf(f0)), __uint_as_float(f2tf(f1)));
                }
            }
        }
    }
}

// ---------------- 3: grouped GEMM2: O[r] = w[r] * (F[r] @ W2[e]) ----------------
// 256 threads. BM=128, BN=128, BK=16, 4-stage cp.async ring (lead 2),
// single barrier per iteration. Warps 2(m) x 4(n); warp tile 64x32.
// grid: (HH/128, TT/128, EE)
__global__ __launch_bounds__(256, 2) void gemm2_kernel(const float* __restrict__ W2)
{
    extern __shared__ float dyn[];
    int e = blockIdx.z;
    int cnt = g_cnt[e];
    int m0 = blockIdx.y * 128;
    if (m0 >= cnt) return;
    int n0 = blockIdx.x * 128;

    float* AsB = dyn;                                    // [NSTAGE][128][AKP]
    float* BsB = dyn + NSTAGE * G2_A_WORDS;              // [NSTAGE][16][BNP]
    __shared__ int rloc[128];
    __shared__ float wloc[128];

    int tid = threadIdx.x;
    int lane = tid & 31;
    int warp = tid >> 5;
    int wm = (warp >> 2) * 64;     // 0 or 64
    int wn = (warp & 3) * 32;      // 0,32,64,96

    if (tid < 128) {
        int mi = m0 + tid;
        if (mi >= cnt) mi = cnt - 1;
        rloc[tid] = g_rows[e * TT + mi];
        wloc[tid] = g_wts[e * TT + mi];
    }
    __syncthreads();

    const float* Bbase = W2 + (size_t)e * II * HH + n0;

    int a_row0 = tid >> 2, a_cg = (tid & 3) * 4;
    int b_kr0 = tid >> 5, b_cg = (tid & 31) * 4;
    const float* a_src0 = g_F + (size_t)rloc[a_row0] * II + a_cg;
    const float* a_src1 = g_F + (size_t)rloc[a_row0 + 64] * II + a_cg;

    float c[4][4][4];
#pragma unroll
    for (int a = 0; a < 4; a++)
#pragma unroll
        for (int b = 0; b < 4; b++)
#pragma unroll
            for (int cc = 0; cc < 4; cc++) c[a][b][cc] = 0.f;

    const int NIT = II / 16;

#pragma unroll
    for (int pre = 0; pre < 2; pre++) {
        int kk = pre * 16;
        float* As = AsB + pre * G2_A_WORDS;
        float* Bs = BsB + pre * G2_B_WORDS;
        cp16(As + a_row0 * AKP + a_cg, a_src0 + kk);
        cp16(As + (a_row0 + 64) * AKP + a_cg, a_src1 + kk);
#pragma unroll
        for (int p = 0; p < 2; p++) {
            int kr = b_kr0 + p * 8;
            cp16(Bs + kr * BNP + b_cg, Bbase + (size_t)(kk + kr) * HH + b_cg);
        }
        CP_COMMIT();
    }

    int buf = 0;
    for (int it = 0; it < NIT; it++) {
        if (it + 2 < NIT) {
            int kk = (it + 2) * 16;
            int s = (it + 2) & (NSTAGE - 1);
            float* As = AsB + s * G2_A_WORDS;
            float* Bs = BsB + s * G2_B_WORDS;
            cp16(As + a_row0 * AKP + a_cg, a_src0 + kk);
            cp16(As + (a_row0 + 64) * AKP + a_cg, a_src1 + kk);
#pragma unroll
            for (int p = 0; p < 2; p++) {
                int kr = b_kr0 + p * 8;
                cp16(Bs + kr * BNP + b_cg, Bbase + (size_t)(kk + kr) * HH + b_cg);
            }
        }
        CP_COMMIT();
        CP_WAIT2();
        __syncthreads();      // single barrier per iteration

        const float* As = AsB + buf * G2_A_WORDS;
        const float* Bs = BsB + buf * G2_B_WORDS;

#pragma unroll
        for (int ks = 0; ks < 16; ks += 8) {
            unsigned a[4][4];
#pragma unroll
            for (int mt = 0; mt < 4; mt++) {
                int r = wm + mt * 16 + (lane >> 2);
                int cc = ks + (lane & 3);
                a[mt][0] = __float_as_uint(As[r * AKP + cc]);
                a[mt][1] = __float_as_uint(As[(r + 8) * AKP + cc]);
                a[mt][2] = __float_as_uint(As[r * AKP + cc + 4]);
                a[mt][3] = __float_as_uint(As[(r + 8) * AKP + cc + 4]);
            }
#pragma unroll
            for (int nt = 0; nt < 4; nt++) {
                int nc = wn + nt * 8 + (lane >> 2);
                int kr = ks + (lane & 3);
                unsigned b[2] = { f2tf(Bs[kr * BNP + nc]), f2tf(Bs[(kr + 4) * BNP + nc]) };
#pragma unroll
                for (int mt = 0; mt < 4; mt++)
                    mma_tf32(c[mt][nt], a[mt], b);
            }
        }
        buf++; if (buf == NSTAGE) buf = 0;
    }

    // epilogue: scale by routing weight, scatter to slot buffer
#pragma unroll
    for (int mt = 0; mt < 4; mt++) {
#pragma unroll
        for (int half = 0; half < 2; half++) {
            int r = wm + mt * 16 + (lane >> 2) + half * 8;
            if (m0 + r < cnt) {
                int rg = rloc[r];
                float wr = wloc[r];
                float* dst = g_slot + (size_t)rg * HH + n0 + wn;
#pragma unroll
                for (int nt = 0; nt < 4; nt++) {
                    float o0 = wr * c[mt][nt][half * 2 + 0];
                    float o1 = wr * c[mt][nt][half * 2 + 1];
                    *reinterpret_cast<float2*>(dst + nt * 8 + (lane & 3) * 2) = make_float2(o0, o1);
                }
            }
        }
    }
}

// ---------------- 4: combine the two expert slots per token ----------------
__global__ void combine_kernel(float* __restrict__ out) {
    int i = blockIdx.x * blockDim.x + threadIdx.x;   // float4 index
    const int n4 = TT * HH / 4;
    if (i >= n4) return;
    int t = i / (HH / 4);
    int h4 = i % (HH / 4);
    float4 a = reinterpret_cast<const float4*>(g_slot + (size_t)(2 * t) * HH)[h4];
    float4 b = reinterpret_cast<const float4*>(g_slot + (size_t)(2 * t + 1) * HH)[h4];
    float4 r = make_float4(a.x + b.x, a.y + b.y, a.z + b.z, a.w + b.w);
    reinterpret_cast<float4*>(out)[i] = r;
}

// ---------------- launch ----------------
extern "C" void kernel_launch(void* const* d_in, const int* in_sizes, int n_in,
                              void* d_out, int out_size) {
    (void)in_sizes; (void)n_in; (void)out_size;
    const float* x   = (const float*)d_in[0];
    const float* Wg  = (const float*)d_in[1];
    const float* W11 = (const float*)d_in[2];
    const float* W12 = (const float*)d_in[3];
    const float* W2  = (const float*)d_in[4];
    float* out = (float*)d_out;

    // raise dynamic smem caps (idempotent; host attribute set, capture-safe)
    cudaFuncSetAttribute(gemm1_kernel, cudaFuncAttributeMaxDynamicSharedMemorySize, G1_SMEM_B);
    cudaFuncSetAttribute(gemm2_kernel, cudaFuncAttributeMaxDynamicSharedMemorySize, G2_SMEM_B);

    zero_cnt_kernel<<<1, 32>>>();
    router_kernel<<<TT / 4, 128>>>(x, Wg);                 // 4 warps/block

    dim3 g1(II / 128, TT / 64, EE);                        // (16, 64, 8)
    gemm1_kernel<<<g1, 256, G1_SMEM_B>>>(x, W11, W12);

    dim3 g2(HH / 128, TT / 128, EE);                       // (8, 32, 8)
    gemm2_kernel<<<g2, 256, G2_SMEM_B>>>(W2);

    combine_kernel<<<(TT * HH / 4 + 255) / 256, 256>>>(out);
}

// round 13
// speedup vs baseline: 1.5384x; 1.4441x over previous
#include <cuda_runtime.h>
#include <cuda_fp16.h>
#include <cstdint>

// Problem constants
#define TT 4096      // B*S tokens
#define HH 1024      // hidden
#define II 2048      // intermediate
#define EE 8         // experts

#define NSTAGE 4     // 4 stages + lead-2 prefetch => no trailing barrier needed
#define RS 40        // smem row stride in halves for BK=32 tiles (80B, 16B-aligned,
                     // conflict-free for m16n8k16 fragment LDS pattern)
#define RSW 20       // same stride in u32 words

// ---------------- scratch (device globals: no allocation allowed) ----------
__device__ __half g_X[(size_t)TT * HH];          // fp16 x (8 MB)
__device__ __half g_F[(size_t)2 * TT * II];      // fused activations fp16 (32 MB)
__device__ __half g_W11T[(size_t)EE * II * HH];  // W11 transposed [e][i][h] fp16 (32 MB)
__device__ __half g_W12T[(size_t)EE * II * HH];  // W12 transposed [e][i][h] fp16 (32 MB)
__device__ __half g_W2T[(size_t)EE * HH * II];   // W2 transposed [e][h][i] fp16 (32 MB)
__device__ float  g_slot[(size_t)2 * TT * HH];   // per-(token,k) outputs f32 (32 MB)
__device__ int    g_cnt[EE];
__device__ int    g_rows[EE * TT];               // stores r = t*2 + k
__device__ float  g_wts[EE * TT];

// ---------------- helpers ----------------
__device__ __forceinline__ void cp16(const void* smem_dst, const void* gmem_src) {
    unsigned s = (unsigned)__cvta_generic_to_shared(smem_dst);
    asm volatile("cp.async.cg.shared.global [%0], [%1], 16;\n" :: "r"(s), "l"(gmem_src));
}
#define CP_COMMIT() asm volatile("cp.async.commit_group;\n" ::: "memory")
#define CP_WAIT2()  asm volatile("cp.async.wait_group 2;\n" ::: "memory")

__device__ __forceinline__ void mma_f16(float c[4], const unsigned a[4], const unsigned b[2]) {
    asm volatile(
        "mma.sync.aligned.m16n8k16.row.col.f32.f16.f16.f32 "
        "{%0,%1,%2,%3}, {%4,%5,%6,%7}, {%8,%9}, {%0,%1,%2,%3};\n"
        : "+f"(c[0]), "+f"(c[1]), "+f"(c[2]), "+f"(c[3])
        : "r"(a[0]), "r"(a[1]), "r"(a[2]), "r"(a[3]), "r"(b[0]), "r"(b[1]));
}

// ---------------- 0: zero expert counters ----------------
__global__ void zero_cnt_kernel() {
    if (threadIdx.x < EE) g_cnt[threadIdx.x] = 0;
}

// ---------------- 0b: transpose + fp16-convert weights --------------------
// src [R][C] fp32 per expert -> dst [C][R] fp16. block 32x8, grid (C/32, R/32, EE)
__global__ void convert_w_kernel(const float* __restrict__ src, int R, int C, int sel) {
    __shared__ float tile[32][33];
    int e = blockIdx.z;
    int c0 = blockIdx.x * 32;
    int r0 = blockIdx.y * 32;
    int tx = threadIdx.x, ty = threadIdx.y;
    const float* s = src + (size_t)e * R * C;
#pragma unroll
    for (int j = 0; j < 4; j++)
        tile[ty + 8 * j][tx] = s[(size_t)(r0 + ty + 8 * j) * C + c0 + tx];
    __syncthreads();
    __half* dstbase = (sel == 0) ? g_W11T : (sel == 1) ? g_W12T : g_W2T;
    __half* d = dstbase + (size_t)e * R * C;
    int ltid = ty * 32 + tx;
    int pr = ltid & 15, cr = ltid >> 4;
#pragma unroll
    for (int j2 = 0; j2 < 2; j2++) {
        int c = cr + 16 * j2;
        __half2 v = __floats2half2_rn(tile[2 * pr][c], tile[2 * pr + 1][c]);
        *reinterpret_cast<__half2*>(d + (size_t)(c0 + c) * R + r0 + 2 * pr) = v;
    }
}

// ---------------- 1: router (1 warp per token); writes fp16 x -------------
__global__ void router_kernel(const float* __restrict__ x, const float* __restrict__ Wg) {
    int t = (blockIdx.x * blockDim.x + threadIdx.x) >> 5;
    int lane = threadIdx.x & 31;
    if (t >= TT) return;
    const float* xr = x + (size_t)t * HH;
    __half* gx = g_X + (size_t)t * HH;
    float acc[EE];
#pragma unroll
    for (int e = 0; e < EE; e++) acc[e] = 0.f;
    for (int h = lane; h < HH; h += 32) {
        float xv = xr[h];
        gx[h] = __float2half_rn(xv);
        const float4* wg = reinterpret_cast<const float4*>(Wg + h * EE);
        float4 w0 = wg[0], w1 = wg[1];
        acc[0] += xv * w0.x; acc[1] += xv * w0.y; acc[2] += xv * w0.z; acc[3] += xv * w0.w;
        acc[4] += xv * w1.x; acc[5] += xv * w1.y; acc[6] += xv * w1.z; acc[7] += xv * w1.w;
    }
#pragma unroll
    for (int off = 16; off > 0; off >>= 1) {
#pragma unroll
        for (int e = 0; e < EE; e++)
            acc[e] += __shfl_xor_sync(0xffffffffu, acc[e], off);
    }
    if (lane == 0) {
        float m = acc[0];
#pragma unroll
        for (int e = 1; e < EE; e++) m = fmaxf(m, acc[e]);
        float p[EE];
        float s = 0.f;
#pragma unroll
        for (int e = 0; e < EE; e++) { p[e] = __expf(acc[e] - m); s += p[e]; }
        float inv = 1.f / s;
        int i0 = 0;
#pragma unroll
        for (int e = 1; e < EE; e++) if (p[e] > p[i0]) i0 = e;
        int i1 = -1;
#pragma unroll
        for (int e = 0; e < EE; e++) {
            if (e == i0) continue;
            if (i1 < 0 || p[e] > p[i1]) i1 = e;
        }
        float s0 = p[i0] * inv, s1 = p[i1] * inv;
        float denom = s0 + s1 + 1e-8f;
        float w0 = s0 / denom, w1 = s1 / denom;
        int pos0 = atomicAdd(&g_cnt[i0], 1);
        g_rows[i0 * TT + pos0] = t * 2 + 0;
        g_wts[i0 * TT + pos0] = w0;
        int pos1 = atomicAdd(&g_cnt[i1], 1);
        g_rows[i1 * TT + pos1] = t * 2 + 1;
        g_wts[i1 * TT + pos1] = w1;
    }
}

// smem sizing (halves)
#define G1_A_H   (64 * RS)          // 2560 halves = 5120 B
#define G1_B_H   (128 * RS)         // 5120 halves = 10240 B
#define G1_SMEM_B  ((NSTAGE * (G1_A_H + 2 * G1_B_H)) * 2)   // 102400 B
#define G2_A_H   (128 * RS)
#define G2_B_H   (128 * RS)
#define G2_SMEM_B  ((NSTAGE * (G2_A_H + G2_B_H)) * 2)       // 81920 B

// ---------------- 2: grouped GEMM1: F = SiLU(X@W11) * (X@W12) -------------
// fp16 m16n8k16. 256 threads. BM=64, BN=128, BK=32. Warps 2(m)x4(n);
// warp tile 32x32 with dual accumulators. 4-stage cp.async, lead-2, 1 barrier.
// grid: (II/128, TT/64, EE)
__global__ __launch_bounds__(256, 2) void gemm1_kernel()
{
    extern __shared__ __half dynh[];
    int e = blockIdx.z;
    int cnt = g_cnt[e];
    int m0 = blockIdx.y * 64;
    if (m0 >= cnt) return;
    int n0 = blockIdx.x * 128;

    __half* AsB  = dynh;                          // [NSTAGE][64][RS]
    __half* B1sB = dynh + NSTAGE * G1_A_H;        // [NSTAGE][128][RS]
    __half* B2sB = B1sB + NSTAGE * G1_B_H;        // [NSTAGE][128][RS]
    __shared__ int rloc[64];

    int tid = threadIdx.x;
    int lane = tid & 31;
    int warp = tid >> 5;
    int gid = lane >> 2;           // groupID
    int tig = lane & 3;            // thread-in-group
    int wm = (warp >> 2) * 32;     // 0 or 32
    int wn = (warp & 3) * 32;      // 0,32,64,96

    if (tid < 64) {
        int mi = m0 + tid;
        if (mi >= cnt) mi = cnt - 1;
        rloc[tid] = g_rows[e * TT + mi];
    }
    __syncthreads();

    // staging coords (16B = 8-half chunks)
    int a_row = tid >> 2, a_ch = (tid & 3) * 8;          // A: 64 rows x 4 chunks, 1/thread
    const __half* a_src = g_X + (size_t)(rloc[a_row] >> 1) * HH + a_ch;
    const __half* b1_src[2];
    const __half* b2_src[2];
    int b_row[2];
#pragma unroll
    for (int p = 0; p < 2; p++) {
        int idx = tid + p * 256;
        b_row[p] = idx >> 2;
        int ch = (idx & 3) * 8;
        b1_src[p] = g_W11T + ((size_t)e * II + n0 + b_row[p]) * HH + ch;
        b2_src[p] = g_W12T + ((size_t)e * II + n0 + b_row[p]) * HH + ch;
    }
    int a_soff = a_row * RS + a_ch;
    int b_soff[2] = { b_row[0] * RS + ((tid & 3) * 8),
                      b_row[1] * RS + (((tid + 256) & 3) * 8) };

    float cG[2][4][4], cV[2][4][4];
#pragma unroll
    for (int a = 0; a < 2; a++)
#pragma unroll
        for (int b = 0; b < 4; b++)
#pragma unroll
            for (int c = 0; c < 4; c++) { cG[a][b][c] = 0.f; cV[a][b][c] = 0.f; }

    const int NIT = HH / 32;   // 32

#pragma unroll
    for (int pre = 0; pre < 2; pre++) {
        int kk = pre * 32;
        __half* As = AsB + pre * G1_A_H;
        __half* B1 = B1sB + pre * G1_B_H;
        __half* B2 = B2sB + pre * G1_B_H;
        cp16(As + a_soff, a_src + kk);
#pragma unroll
        for (int p = 0; p < 2; p++) {
            cp16(B1 + b_soff[p], b1_src[p] + kk);
            cp16(B2 + b_soff[p], b2_src[p] + kk);
        }
        CP_COMMIT();
    }

    int buf = 0;
    for (int it = 0; it < NIT; it++) {
        if (it + 2 < NIT) {
            int kk = (it + 2) * 32;
            int s = (it + 2) & (NSTAGE - 1);
            __half* As = AsB + s * G1_A_H;
            __half* B1 = B1sB + s * G1_B_H;
            __half* B2 = B2sB + s * G1_B_H;
            cp16(As + a_soff, a_src + kk);
#pragma unroll
            for (int p = 0; p < 2; p++) {
                cp16(B1 + b_soff[p], b1_src[p] + kk);
                cp16(B2 + b_soff[p], b2_src[p] + kk);
            }
        }
        CP_COMMIT();
        CP_WAIT2();
        __syncthreads();

        const uint32_t* Au = (const uint32_t*)(AsB + buf * G1_A_H);
        const uint32_t* B1u = (const uint32_t*)(B1sB + buf * G1_B_H);
        const uint32_t* B2u = (const uint32_t*)(B2sB + buf * G1_B_H);

#pragma unroll
        for (int ks = 0; ks < 2; ks++) {     // two k16 slabs per BK=32
            unsigned a[2][4];
#pragma unroll
            for (int mt = 0; mt < 2; mt++) {
                int base = (wm + mt * 16 + gid) * RSW + ks * 8 + tig;
                a[mt][0] = Au[base];
                a[mt][1] = Au[base + 8 * RSW];
                a[mt][2] = Au[base + 4];
                a[mt][3] = Au[base + 8 * RSW + 4];
            }
#pragma unroll
            for (int nt = 0; nt < 4; nt++) {
                int bb = (wn + nt * 8 + gid) * RSW + ks * 8 + tig;
                unsigned b1[2] = { B1u[bb], B1u[bb + 4] };
                unsigned b2[2] = { B2u[bb], B2u[bb + 4] };
#pragma unroll
                for (int mt = 0; mt < 2; mt++) {
                    mma_f16(cG[mt][nt], a[mt], b1);
                    mma_f16(cV[mt][nt], a[mt], b2);
                }
            }
        }
        buf++; if (buf == NSTAGE) buf = 0;
    }

    // epilogue: f = g * sigmoid(g) * v -> g_F[r] (fp16)
#pragma unroll
    for (int mt = 0; mt < 2; mt++) {
#pragma unroll
        for (int half = 0; half < 2; half++) {
            int r = wm + mt * 16 + gid + half * 8;
            if (m0 + r < cnt) {
                int rg = rloc[r];
                __half* dst = g_F + (size_t)rg * II + n0 + wn;
#pragma unroll
                for (int nt = 0; nt < 4; nt++) {
                    float g0 = cG[mt][nt][half * 2 + 0], g1 = cG[mt][nt][half * 2 + 1];
                    float v0 = cV[mt][nt][half * 2 + 0], v1 = cV[mt][nt][half * 2 + 1];
                    float f0 = g0 * v0 / (1.f + __expf(-g0));
                    float f1 = g1 * v1 / (1.f + __expf(-g1));
                    *reinterpret_cast<__half2*>(dst + nt * 8 + tig * 2) =
                        __floats2half2_rn(f0, f1);
                }
            }
        }
    }
}

// ---------------- 3: grouped GEMM2: O[r] = w[r] * (F[r] @ W2[e]) ----------
// fp16 m16n8k16. 256 threads. BM=128, BN=128, BK=32. Warps 2(m)x4(n);
// warp tile 64x32. 4-stage cp.async, lead-2, 1 barrier.
// grid: (HH/128, TT/128, EE)
__global__ __launch_bounds__(256, 2) void gemm2_kernel()
{
    extern __shared__ __half dynh[];
    int e = blockIdx.z;
    int cnt = g_cnt[e];
    int m0 = blockIdx.y * 128;
    if (m0 >= cnt) return;
    int n0 = blockIdx.x * 128;

    __half* AsB = dynh;                           // [NSTAGE][128][RS]
    __half* BsB = dynh + NSTAGE * G2_A_H;         // [NSTAGE][128][RS]
    __shared__ int rloc[128];
    __shared__ float wloc[128];

    int tid = threadIdx.x;
    int lane = tid & 31;
    int warp = tid >> 5;
    int gid = lane >> 2;
    int tig = lane & 3;
    int wm = (warp >> 2) * 64;     // 0 or 64
    int wn = (warp & 3) * 32;      // 0,32,64,96

    if (tid < 128) {
        int mi = m0 + tid;
        if (mi >= cnt) mi = cnt - 1;
        rloc[tid] = g_rows[e * TT + mi];
        wloc[tid] = g_wts[e * TT + mi];
    }
    __syncthreads();

    const __half* a_src[2];
    const __half* b_src[2];
    int soff[2];
#pragma unroll
    for (int p = 0; p < 2; p++) {
        int idx = tid + p * 256;
        int row = idx >> 2;
        int ch = (idx & 3) * 8;
        a_src[p] = g_F + (size_t)rloc[row] * II + ch;
        b_src[p] = g_W2T + ((size_t)e * HH + n0 + row) * II + ch;
        soff[p] = row * RS + ch;
    }

    float c[4][4][4];
#pragma unroll
    for (int a = 0; a < 4; a++)
#pragma unroll
        for (int b = 0; b < 4; b++)
#pragma unroll
            for (int cc = 0; cc < 4; cc++) c[a][b][cc] = 0.f;

    const int NIT = II / 32;   // 64

#pragma unroll
    for (int pre = 0; pre < 2; pre++) {
        int kk = pre * 32;
        __half* As = AsB + pre * G2_A_H;
        __half* Bs = BsB + pre * G2_B_H;
#pragma unroll
        for (int p = 0; p < 2; p++) {
            cp16(As + soff[p], a_src[p] + kk);
            cp16(Bs + soff[p], b_src[p] + kk);
        }
        CP_COMMIT();
    }

    int buf = 0;
    for (int it = 0; it < NIT; it++) {
        if (it + 2 < NIT) {
            int kk = (it + 2) * 32;
            int s = (it + 2) & (NSTAGE - 1);
            __half* As = AsB + s * G2_A_H;
            __half* Bs = BsB + s * G2_B_H;
#pragma unroll
            for (int p = 0; p < 2; p++) {
                cp16(As + soff[p], a_src[p] + kk);
                cp16(Bs + soff[p], b_src[p] + kk);
            }
        }
        CP_COMMIT();
        CP_WAIT2();
        __syncthreads();

        const uint32_t* Au = (const uint32_t*)(AsB + buf * G2_A_H);
        const uint32_t* Bu = (const uint32_t*)(BsB + buf * G2_B_H);

#pragma unroll
        for (int ks = 0; ks < 2; ks++) {
            unsigned a[4][4];
#pragma unroll
            for (int mt = 0; mt < 4; mt++) {
                int base = (wm + mt * 16 + gid) * RSW + ks * 8 + tig;
                a[mt][0] = Au[base];
                a[mt][1] = Au[base + 8 * RSW];
                a[mt][2] = Au[base + 4];
                a[mt][3] = Au[base + 8 * RSW + 4];
            }
#pragma unroll
            for (int nt = 0; nt < 4; nt++) {
                int bb = (wn + nt * 8 + gid) * RSW + ks * 8 + tig;
                unsigned b[2] = { Bu[bb], Bu[bb + 4] };
#pragma unroll
                for (int mt = 0; mt < 4; mt++)
                    mma_f16(c[mt][nt], a[mt], b);
            }
        }
        buf++; if (buf == NSTAGE) buf = 0;
    }

    // epilogue: scale by routing weight, scatter to slot buffer
#pragma unroll
    for (int mt = 0; mt < 4; mt++) {
#pragma unroll
        for (int half = 0; half < 2; half++) {
            int r = wm + mt * 16 + gid + half * 8;
            if (m0 + r < cnt) {
                int rg = rloc[r];
                float wr = wloc[r];
                float* dst = g_slot + (size_t)rg * HH + n0 + wn;
#pragma unroll
                for (int nt = 0; nt < 4; nt++) {
                    float o0 = wr * c[mt][nt][half * 2 + 0];
                    float o1 = wr * c[mt][nt][half * 2 + 1];
                    *reinterpret_cast<float2*>(dst + nt * 8 + tig * 2) = make_float2(o0, o1);
                }
            }
        }
    }
}

// ---------------- 4: combine the two expert slots per token ----------------
__global__ void combine_kernel(float* __restrict__ out) {
    int i = blockIdx.x * blockDim.x + threadIdx.x;
    const int n4 = TT * HH / 4;
    if (i >= n4) return;
    int t = i / (HH / 4);
    int h4 = i % (HH / 4);
    float4 a = reinterpret_cast<const float4*>(g_slot + (size_t)(2 * t) * HH)[h4];
    float4 b = reinterpret_cast<const float4*>(g_slot + (size_t)(2 * t + 1) * HH)[h4];
    float4 r = make_float4(a.x + b.x, a.y + b.y, a.z + b.z, a.w + b.w);
    reinterpret_cast<float4*>(out)[i] = r;
}

// ---------------- launch ----------------
extern "C" void kernel_launch(void* const* d_in, const int* in_sizes, int n_in,
                              void* d_out, int out_size) {
    (void)in_sizes; (void)n_in; (void)out_size;
    const float* x   = (const float*)d_in[0];
    const float* Wg  = (const float*)d_in[1];
    const float* W11 = (const float*)d_in[2];
    const float* W12 = (const float*)d_in[3];
    const float* W2  = (const float*)d_in[4];
    float* out = (float*)d_out;

    cudaFuncSetAttribute(gemm1_kernel, cudaFuncAttributeMaxDynamicSharedMemorySize, G1_SMEM_B);
    cudaFuncSetAttribute(gemm2_kernel, cudaFuncAttributeMaxDynamicSharedMemorySize, G2_SMEM_B);

    zero_cnt_kernel<<<1, 32>>>();

    // weight convert+transpose prepasses (fp32 -> fp16, K-contiguous)
    convert_w_kernel<<<dim3(II / 32, HH / 32, EE), dim3(32, 8)>>>(W11, HH, II, 0);
    convert_w_kernel<<<dim3(II / 32, HH / 32, EE), dim3(32, 8)>>>(W12, HH, II, 1);
    convert_w_kernel<<<dim3(HH / 32, II / 32, EE), dim3(32, 8)>>>(W2, II, HH, 2);

    router_kernel<<<TT / 4, 128>>>(x, Wg);

    dim3 g1(II / 128, TT / 64, EE);                        // (16, 64, 8)
    gemm1_kernel<<<g1, 256, G1_SMEM_B>>>();

    dim3 g2(HH / 128, TT / 128, EE);                       // (8, 32, 8)
    gemm2_kernel<<<g2, 256, G2_SMEM_B>>>();

    combine_kernel<<<(TT * HH / 4 + 255) / 256, 256>>>(out);
}

// round 14
// speedup vs baseline: 1.5397x; 1.0009x over previous
#include <cuda_runtime.h>
#include <cuda_fp16.h>
#include <cstdint>

// Problem constants
#define TT 4096      // B*S tokens
#define HH 1024      // hidden
#define II 2048      // intermediate
#define EE 8         // experts

#define NSTAGE 4     // 4 stages + lead-2 prefetch => no trailing barrier needed
#define RS 40        // smem row stride in halves (80B, 16B-aligned, conflict-free)
#define RSW 20       // same stride in u32 words

// ---------------- scratch (device globals: no allocation allowed) ----------
__device__ __half g_X[(size_t)TT * HH];          // fp16 x (8 MB)
__device__ __half g_F[(size_t)2 * TT * II];      // fused activations fp16 (32 MB)
__device__ __half g_W11T[(size_t)EE * II * HH];  // W11 transposed [e][i][h] fp16 (32 MB)
__device__ __half g_W12T[(size_t)EE * II * HH];  // W12 transposed [e][i][h] fp16 (32 MB)
__device__ __half g_W2T[(size_t)EE * HH * II];   // W2 transposed [e][h][i] fp16 (32 MB)
__device__ int    g_cnt[EE];
__device__ int    g_rows[EE * TT];               // stores r = t*2 + k
__device__ float  g_wts[EE * TT];

// ---------------- helpers ----------------
__device__ __forceinline__ void cp16(const void* smem_dst, const void* gmem_src) {
    unsigned s = (unsigned)__cvta_generic_to_shared(smem_dst);
    asm volatile("cp.async.cg.shared.global [%0], [%1], 16;\n" :: "r"(s), "l"(gmem_src));
}
#define CP_COMMIT() asm volatile("cp.async.commit_group;\n" ::: "memory")
#define CP_WAIT2()  asm volatile("cp.async.wait_group 2;\n" ::: "memory")

__device__ __forceinline__ void mma_f16(float c[4], const unsigned a[4], const unsigned b[2]) {
    asm volatile(
        "mma.sync.aligned.m16n8k16.row.col.f32.f16.f16.f32 "
        "{%0,%1,%2,%3}, {%4,%5,%6,%7}, {%8,%9}, {%0,%1,%2,%3};\n"
        : "+f"(c[0]), "+f"(c[1]), "+f"(c[2]), "+f"(c[3])
        : "r"(a[0]), "r"(a[1]), "r"(a[2]), "r"(a[3]), "r"(b[0]), "r"(b[1]));
}

__device__ __forceinline__ void red_add_f32(float* p, float v) {
    asm volatile("red.global.add.f32 [%0], %1;" :: "l"(p), "f"(v) : "memory");
}

// ---------------- 0: zero expert counters ----------------
__global__ void zero_cnt_kernel() {
    if (threadIdx.x < EE) g_cnt[threadIdx.x] = 0;
}

// ---------------- 0a: zero the output (RED target) ----------------
__global__ void zero_out_kernel(float* __restrict__ out) {
    int i = blockIdx.x * blockDim.x + threadIdx.x;
    if (i < TT * HH / 4)
        reinterpret_cast<float4*>(out)[i] = make_float4(0.f, 0.f, 0.f, 0.f);
}

// ---------------- 0b: transpose + fp16-convert all 3 weights (fused) ------
// grid (64, 32, 3*EE); sel = z / EE. W11/W12: R=HH,C=II. W2: R=II,C=HH (swap).
__global__ void convert_w_kernel(const float* __restrict__ W11,
                                 const float* __restrict__ W12,
                                 const float* __restrict__ W2) {
    __shared__ float tile[32][33];
    int sel = blockIdx.z / EE;
    int e = blockIdx.z % EE;
    int bx = blockIdx.x, by = blockIdx.y;
    int R, C;
    const float* src;
    __half* dstbase;
    if (sel == 0)      { R = HH; C = II; src = W11; dstbase = g_W11T; }
    else if (sel == 1) { R = HH; C = II; src = W12; dstbase = g_W12T; }
    else               { R = II; C = HH; src = W2;  dstbase = g_W2T;
                         int t = bx; bx = by; by = t; }   // grid shaped for C=II
    int c0 = bx * 32, r0 = by * 32;
    int tx = threadIdx.x, ty = threadIdx.y;
    const float* s = src + (size_t)e * R * C;
#pragma unroll
    for (int j = 0; j < 4; j++)
        tile[ty + 8 * j][tx] = s[(size_t)(r0 + ty + 8 * j) * C + c0 + tx];
    __syncthreads();
    __half* d = dstbase + (size_t)e * R * C;
    int ltid = ty * 32 + tx;
    int pr = ltid & 15, cr = ltid >> 4;
#pragma unroll
    for (int j2 = 0; j2 < 2; j2++) {
        int c = cr + 16 * j2;
        __half2 v = __floats2half2_rn(tile[2 * pr][c], tile[2 * pr + 1][c]);
        *reinterpret_cast<__half2*>(d + (size_t)(c0 + c) * R + r0 + 2 * pr) = v;
    }
}

// ---------------- 1: router (1 warp per token); writes fp16 x -------------
__global__ void router_kernel(const float* __restrict__ x, const float* __restrict__ Wg) {
    int t = (blockIdx.x * blockDim.x + threadIdx.x) >> 5;
    int lane = threadIdx.x & 31;
    if (t >= TT) return;
    const float* xr = x + (size_t)t * HH;
    __half* gx = g_X + (size_t)t * HH;
    float acc[EE];
#pragma unroll
    for (int e = 0; e < EE; e++) acc[e] = 0.f;
    for (int h = lane; h < HH; h += 32) {
        float xv = xr[h];
        gx[h] = __float2half_rn(xv);
        const float4* wg = reinterpret_cast<const float4*>(Wg + h * EE);
        float4 w0 = wg[0], w1 = wg[1];
        acc[0] += xv * w0.x; acc[1] += xv * w0.y; acc[2] += xv * w0.z; acc[3] += xv * w0.w;
        acc[4] += xv * w1.x; acc[5] += xv * w1.y; acc[6] += xv * w1.z; acc[7] += xv * w1.w;
    }
#pragma unroll
    for (int off = 16; off > 0; off >>= 1) {
#pragma unroll
        for (int e = 0; e < EE; e++)
            acc[e] += __shfl_xor_sync(0xffffffffu, acc[e], off);
    }
    if (lane == 0) {
        float m = acc[0];
#pragma unroll
        for (int e = 1; e < EE; e++) m = fmaxf(m, acc[e]);
        float p[EE];
        float s = 0.f;
#pragma unroll
        for (int e = 0; e < EE; e++) { p[e] = __expf(acc[e] - m); s += p[e]; }
        float inv = 1.f / s;
        int i0 = 0;
#pragma unroll
        for (int e = 1; e < EE; e++) if (p[e] > p[i0]) i0 = e;
        int i1 = -1;
#pragma unroll
        for (int e = 0; e < EE; e++) {
            if (e == i0) continue;
            if (i1 < 0 || p[e] > p[i1]) i1 = e;
        }
        float s0 = p[i0] * inv, s1 = p[i1] * inv;
        float denom = s0 + s1 + 1e-8f;
        float w0 = s0 / denom, w1 = s1 / denom;
        int pos0 = atomicAdd(&g_cnt[i0], 1);
        g_rows[i0 * TT + pos0] = t * 2 + 0;
        g_wts[i0 * TT + pos0] = w0;
        int pos1 = atomicAdd(&g_cnt[i1], 1);
        g_rows[i1 * TT + pos1] = t * 2 + 1;
        g_wts[i1 * TT + pos1] = w1;
    }
}

// smem sizing (halves)
#define G1_A_H   (64 * RS)
#define G1_B_H   (128 * RS)
#define G1_SMEM_B  ((NSTAGE * (G1_A_H + 2 * G1_B_H)) * 2)   // 102400 B
#define G2_A_H   (128 * RS)
#define G2_B_H   (128 * RS)
#define G2_SMEM_B  ((NSTAGE * (G2_A_H + G2_B_H)) * 2)       // 81920 B

// ---------------- 2: grouped GEMM1: F = SiLU(X@W11) * (X@W12) -------------
// fp16 m16n8k16. 256 threads. BM=64, BN=128, BK=32. Warps 2(m)x4(n);
// warp tile 32x32 dual accum. 4-stage cp.async, lead-2, 1 barrier.
// grid: (II/128, TT/64, EE)
__global__ __launch_bounds__(256, 2) void gemm1_kernel()
{
    extern __shared__ __half dynh[];
    int e = blockIdx.z;
    int cnt = g_cnt[e];
    int m0 = blockIdx.y * 64;
    if (m0 >= cnt) return;
    int n0 = blockIdx.x * 128;

    __half* AsB  = dynh;                          // [NSTAGE][64][RS]
    __half* B1sB = dynh + NSTAGE * G1_A_H;        // [NSTAGE][128][RS]
    __half* B2sB = B1sB + NSTAGE * G1_B_H;        // [NSTAGE][128][RS]
    __shared__ int rloc[64];

    int tid = threadIdx.x;
    int lane = tid & 31;
    int warp = tid >> 5;
    int gid = lane >> 2;
    int tig = lane & 3;
    int wm = (warp >> 2) * 32;
    int wn = (warp & 3) * 32;

    if (tid < 64) {
        int mi = m0 + tid;
        if (mi >= cnt) mi = cnt - 1;
        rloc[tid] = g_rows[e * TT + mi];
    }
    __syncthreads();

    int a_row = tid >> 2, a_ch = (tid & 3) * 8;
    const __half* a_src = g_X + (size_t)(rloc[a_row] >> 1) * HH + a_ch;
    const __half* b1_src[2];
    const __half* b2_src[2];
    int b_soff[2];
#pragma unroll
    for (int p = 0; p < 2; p++) {
        int idx = tid + p * 256;
        int row = idx >> 2;
        int ch = (idx & 3) * 8;
        b1_src[p] = g_W11T + ((size_t)e * II + n0 + row) * HH + ch;
        b2_src[p] = g_W12T + ((size_t)e * II + n0 + row) * HH + ch;
        b_soff[p] = row * RS + ch;
    }
    int a_soff = a_row * RS + a_ch;

    float cG[2][4][4], cV[2][4][4];
#pragma unroll
    for (int a = 0; a < 2; a++)
#pragma unroll
        for (int b = 0; b < 4; b++)
#pragma unroll
            for (int c = 0; c < 4; c++) { cG[a][b][c] = 0.f; cV[a][b][c] = 0.f; }

    const int NIT = HH / 32;   // 32

#pragma unroll
    for (int pre = 0; pre < 2; pre++) {
        int kk = pre * 32;
        __half* As = AsB + pre * G1_A_H;
        __half* B1 = B1sB + pre * G1_B_H;
        __half* B2 = B2sB + pre * G1_B_H;
        cp16(As + a_soff, a_src + kk);
#pragma unroll
        for (int p = 0; p < 2; p++) {
            cp16(B1 + b_soff[p], b1_src[p] + kk);
            cp16(B2 + b_soff[p], b2_src[p] + kk);
        }
        CP_COMMIT();
    }

    int buf = 0;
    for (int it = 0; it < NIT; it++) {
        if (it + 2 < NIT) {
            int kk = (it + 2) * 32;
            int s = (it + 2) & (NSTAGE - 1);
            __half* As = AsB + s * G1_A_H;
            __half* B1 = B1sB + s * G1_B_H;
            __half* B2 = B2sB + s * G1_B_H;
            cp16(As + a_soff, a_src + kk);
#pragma unroll
            for (int p = 0; p < 2; p++) {
                cp16(B1 + b_soff[p], b1_src[p] + kk);
                cp16(B2 + b_soff[p], b2_src[p] + kk);
            }
        }
        CP_COMMIT();
        CP_WAIT2();
        __syncthreads();

        const uint32_t* Au = (const uint32_t*)(AsB + buf * G1_A_H);
        const uint32_t* B1u = (const uint32_t*)(B1sB + buf * G1_B_H);
        const uint32_t* B2u = (const uint32_t*)(B2sB + buf * G1_B_H);

#pragma unroll
        for (int ks = 0; ks < 2; ks++) {
            unsigned a[2][4];
#pragma unroll
            for (int mt = 0; mt < 2; mt++) {
                int base = (wm + mt * 16 + gid) * RSW + ks * 8 + tig;
                a[mt][0] = Au[base];
                a[mt][1] = Au[base + 8 * RSW];
                a[mt][2] = Au[base + 4];
                a[mt][3] = Au[base + 8 * RSW + 4];
            }
#pragma unroll
            for (int nt = 0; nt < 4; nt++) {
                int bb = (wn + nt * 8 + gid) * RSW + ks * 8 + tig;
                unsigned b1[2] = { B1u[bb], B1u[bb + 4] };
                unsigned b2[2] = { B2u[bb], B2u[bb + 4] };
#pragma unroll
                for (int mt = 0; mt < 2; mt++) {
                    mma_f16(cG[mt][nt], a[mt], b1);
                    mma_f16(cV[mt][nt], a[mt], b2);
                }
            }
        }
        buf++; if (buf == NSTAGE) buf = 0;
    }

    // epilogue: f = g * sigmoid(g) * v -> g_F[r] (fp16)
#pragma unroll
    for (int mt = 0; mt < 2; mt++) {
#pragma unroll
        for (int half = 0; half < 2; half++) {
            int r = wm + mt * 16 + gid + half * 8;
            if (m0 + r < cnt) {
                int rg = rloc[r];
                __half* dst = g_F + (size_t)rg * II + n0 + wn;
#pragma unroll
                for (int nt = 0; nt < 4; nt++) {
                    float g0 = cG[mt][nt][half * 2 + 0], g1 = cG[mt][nt][half * 2 + 1];
                    float v0 = cV[mt][nt][half * 2 + 0], v1 = cV[mt][nt][half * 2 + 1];
                    float f0 = g0 * v0 / (1.f + __expf(-g0));
                    float f1 = g1 * v1 / (1.f + __expf(-g1));
                    *reinterpret_cast<__half2*>(dst + nt * 8 + tig * 2) =
                        __floats2half2_rn(f0, f1);
                }
            }
        }
    }
}

// ---------------- 3: grouped GEMM2: out += w[r] * (F[r] @ W2[e]) ----------
// fp16 m16n8k16. 256 threads. BM=128, BN=128, BK=32. Warps 2(m)x4(n);
// warp tile 64x32. Epilogue: red.global.add directly into out (2 contributions
// per element, fp add commutative -> deterministic).
// grid: (HH/128, TT/128, EE)
__global__ __launch_bounds__(256, 2) void gemm2_kernel(float* __restrict__ out)
{
    extern __shared__ __half dynh[];
    int e = blockIdx.z;
    int cnt = g_cnt[e];
    int m0 = blockIdx.y * 128;
    if (m0 >= cnt) return;
    int n0 = blockIdx.x * 128;

    __half* AsB = dynh;                           // [NSTAGE][128][RS]
    __half* BsB = dynh + NSTAGE * G2_A_H;         // [NSTAGE][128][RS]
    __shared__ int rloc[128];
    __shared__ float wloc[128];

    int tid = threadIdx.x;
    int lane = tid & 31;
    int warp = tid >> 5;
    int gid = lane >> 2;
    int tig = lane & 3;
    int wm = (warp >> 2) * 64;
    int wn = (warp & 3) * 32;

    if (tid < 128) {
        int mi = m0 + tid;
        if (mi >= cnt) mi = cnt - 1;
        rloc[tid] = g_rows[e * TT + mi];
        wloc[tid] = g_wts[e * TT + mi];
    }
    __syncthreads();

    const __half* a_src[2];
    const __half* b_src[2];
    int soff[2];
#pragma unroll
    for (int p = 0; p < 2; p++) {
        int idx = tid + p * 256;
        int row = idx >> 2;
        int ch = (idx & 3) * 8;
        a_src[p] = g_F + (size_t)rloc[row] * II + ch;
        b_src[p] = g_W2T + ((size_t)e * HH + n0 + row) * II + ch;
        soff[p] = row * RS + ch;
    }

    float c[4][4][4];
#pragma unroll
    for (int a = 0; a < 4; a++)
#pragma unroll
        for (int b = 0; b < 4; b++)
#pragma unroll
            for (int cc = 0; cc < 4; cc++) c[a][b][cc] = 0.f;

    const int NIT = II / 32;   // 64

#pragma unroll
    for (int pre = 0; pre < 2; pre++) {
        int kk = pre * 32;
        __half* As = AsB + pre * G2_A_H;
        __half* Bs = BsB + pre * G2_B_H;
#pragma unroll
        for (int p = 0; p < 2; p++) {
            cp16(As + soff[p], a_src[p] + kk);
            cp16(Bs + soff[p], b_src[p] + kk);
        }
        CP_COMMIT();
    }

    int buf = 0;
    for (int it = 0; it < NIT; it++) {
        if (it + 2 < NIT) {
            int kk = (it + 2) * 32;
            int s = (it + 2) & (NSTAGE - 1);
            __half* As = AsB + s * G2_A_H;
            __half* Bs = BsB + s * G2_B_H;
#pragma unroll
            for (int p = 0; p < 2; p++) {
                cp16(As + soff[p], a_src[p] + kk);
                cp16(Bs + soff[p], b_src[p] + kk);
            }
        }
        CP_COMMIT();
        CP_WAIT2();
        __syncthreads();

        const uint32_t* Au = (const uint32_t*)(AsB + buf * G2_A_H);
        const uint32_t* Bu = (const uint32_t*)(BsB + buf * G2_B_H);

#pragma unroll
        for (int ks = 0; ks < 2; ks++) {
            unsigned a[4][4];
#pragma unroll
            for (int mt = 0; mt < 4; mt++) {
                int base = (wm + mt * 16 + gid) * RSW + ks * 8 + tig;
                a[mt][0] = Au[base];
                a[mt][1] = Au[base + 8 * RSW];
                a[mt][2] = Au[base + 4];
                a[mt][3] = Au[base + 8 * RSW + 4];
            }
#pragma unroll
            for (int nt = 0; nt < 4; nt++) {
                int bb = (wn + nt * 8 + gid) * RSW + ks * 8 + tig;
                unsigned b[2] = { Bu[bb], Bu[bb + 4] };
#pragma unroll
                for (int mt = 0; mt < 4; mt++)
                    mma_f16(c[mt][nt], a[mt], b);
            }
        }
        buf++; if (buf == NSTAGE) buf = 0;
    }

    // epilogue: scale by routing weight, RED into out[token]
#pragma unroll
    for (int mt = 0; mt < 4; mt++) {
#pragma unroll
        for (int half = 0; half < 2; half++) {
            int r = wm + mt * 16 + gid + half * 8;
            if (m0 + r < cnt) {
                int tok = rloc[r] >> 1;
                float wr = wloc[r];
                float* dst = out + (size_t)tok * HH + n0 + wn;
#pragma unroll
                for (int nt = 0; nt < 4; nt++) {
                    red_add_f32(dst + nt * 8 + tig * 2 + 0, wr * c[mt][nt][half * 2 + 0]);
                    red_add_f32(dst + nt * 8 + tig * 2 + 1, wr * c[mt][nt][half * 2 + 1]);
                }
            }
        }
    }
}

// ---------------- launch ----------------
extern "C" void kernel_launch(void* const* d_in, const int* in_sizes, int n_in,
                              void* d_out, int out_size) {
    (void)in_sizes; (void)n_in; (void)out_size;
    const float* x   = (const float*)d_in[0];
    const float* Wg  = (const float*)d_in[1];
    const float* W11 = (const float*)d_in[2];
    const float* W12 = (const float*)d_in[3];
    const float* W2  = (const float*)d_in[4];
    float* out = (float*)d_out;

    cudaFuncSetAttribute(gemm1_kernel, cudaFuncAttributeMaxDynamicSharedMemorySize, G1_SMEM_B);
    cudaFuncSetAttribute(gemm2_kernel, cudaFuncAttributeMaxDynamicSharedMemorySize, G2_SMEM_B);

    zero_cnt_kernel<<<1, 32>>>();
    zero_out_kernel<<<(TT * HH / 4 + 255) / 256, 256>>>(out);

    // fused weight convert+transpose (fp32 -> fp16, K-contiguous)
    convert_w_kernel<<<dim3(II / 32, HH / 32, 3 * EE), dim3(32, 8)>>>(W11, W12, W2);

    router_kernel<<<TT / 4, 128>>>(x, Wg);

    dim3 g1(II / 128, TT / 64, EE);                        // (16, 64, 8)
    gemm1_kernel<<<g1, 256, G1_SMEM_B>>>();

    dim3 g2(HH / 128, TT / 128, EE);                       // (8, 32, 8)
    gemm2_kernel<<<g2, 256, G2_SMEM_B>>>(out);
}

// round 15
// speedup vs baseline: 1.6919x; 1.0988x over previous
#include <cuda_runtime.h>
#include <cuda_fp16.h>
#include <cstdint>

// Problem constants
#define TT 4096      // B*S tokens
#define HH 1024      // hidden
#define II 2048      // intermediate
#define EE 8         // experts

#define NSTAGE 4     // 4 stages + lead-2 prefetch => no trailing barrier needed
#define RS 40        // smem row stride in halves (80B; conflict-free for LDSM 8-row groups)

// ---------------- scratch (device globals: no allocation allowed) ----------
__device__ __half g_X[(size_t)TT * HH];          // fp16 x (8 MB)
__device__ __half g_F[(size_t)2 * TT * II];      // fused activations fp16 (32 MB)
__device__ __half g_W11T[(size_t)EE * II * HH];  // W11 transposed [e][i][h] fp16 (32 MB)
__device__ __half g_W12T[(size_t)EE * II * HH];  // W12 transposed [e][i][h] fp16 (32 MB)
__device__ __half g_W2T[(size_t)EE * HH * II];   // W2 transposed [e][h][i] fp16 (32 MB)
__device__ int    g_cnt[EE];
__device__ int    g_rows[EE * TT];               // stores r = t*2 + k
__device__ float  g_wts[EE * TT];

// ---------------- helpers ----------------
__device__ __forceinline__ void cp16(const void* smem_dst, const void* gmem_src) {
    unsigned s = (unsigned)__cvta_generic_to_shared(smem_dst);
    asm volatile("cp.async.cg.shared.global [%0], [%1], 16;\n" :: "r"(s), "l"(gmem_src));
}
#define CP_COMMIT() asm volatile("cp.async.commit_group;\n" ::: "memory")
#define CP_WAIT2()  asm volatile("cp.async.wait_group 2;\n" ::: "memory")

__device__ __forceinline__ void mma_f16(float c[4], const unsigned a[4], const unsigned b[2]) {
    asm volatile(
        "mma.sync.aligned.m16n8k16.row.col.f32.f16.f16.f32 "
        "{%0,%1,%2,%3}, {%4,%5,%6,%7}, {%8,%9}, {%0,%1,%2,%3};\n"
        : "+f"(c[0]), "+f"(c[1]), "+f"(c[2]), "+f"(c[3])
        : "r"(a[0]), "r"(a[1]), "r"(a[2]), "r"(a[3]), "r"(b[0]), "r"(b[1]));
}

__device__ __forceinline__ void ldsm4(unsigned r[4], const __half* p) {
    unsigned a = (unsigned)__cvta_generic_to_shared(p);
    asm volatile("ldmatrix.sync.aligned.m8n8.x4.shared.b16 {%0,%1,%2,%3}, [%4];"
                 : "=r"(r[0]), "=r"(r[1]), "=r"(r[2]), "=r"(r[3]) : "r"(a));
}

__device__ __forceinline__ void red_add_f32(float* p, float v) {
    asm volatile("red.global.add.f32 [%0], %1;" :: "l"(p), "f"(v) : "memory");
}

// ---------------- 0: zero expert counters ----------------
__global__ void zero_cnt_kernel() {
    if (threadIdx.x < EE) g_cnt[threadIdx.x] = 0;
}

// ---------------- 0a: zero the output (RED target) ----------------
__global__ void zero_out_kernel(float* __restrict__ out) {
    int i = blockIdx.x * blockDim.x + threadIdx.x;
    if (i < TT * HH / 4)
        reinterpret_cast<float4*>(out)[i] = make_float4(0.f, 0.f, 0.f, 0.f);
}

// ---------------- 0b: transpose + fp16-convert all 3 weights (fused) ------
__global__ void convert_w_kernel(const float* __restrict__ W11,
                                 const float* __restrict__ W12,
                                 const float* __restrict__ W2) {
    __shared__ float tile[32][33];
    int sel = blockIdx.z / EE;
    int e = blockIdx.z % EE;
    int bx = blockIdx.x, by = blockIdx.y;
    int R, C;
    const float* src;
    __half* dstbase;
    if (sel == 0)      { R = HH; C = II; src = W11; dstbase = g_W11T; }
    else if (sel == 1) { R = HH; C = II; src = W12; dstbase = g_W12T; }
    else               { R = II; C = HH; src = W2;  dstbase = g_W2T;
                         int t = bx; bx = by; by = t; }
    int c0 = bx * 32, r0 = by * 32;
    int tx = threadIdx.x, ty = threadIdx.y;
    const float* s = src + (size_t)e * R * C;
#pragma unroll
    for (int j = 0; j < 4; j++)
        tile[ty + 8 * j][tx] = s[(size_t)(r0 + ty + 8 * j) * C + c0 + tx];
    __syncthreads();
    __half* d = dstbase + (size_t)e * R * C;
    int ltid = ty * 32 + tx;
    int pr = ltid & 15, cr = ltid >> 4;
#pragma unroll
    for (int j2 = 0; j2 < 2; j2++) {
        int c = cr + 16 * j2;
        __half2 v = __floats2half2_rn(tile[2 * pr][c], tile[2 * pr + 1][c]);
        *reinterpret_cast<__half2*>(d + (size_t)(c0 + c) * R + r0 + 2 * pr) = v;
    }
}

// ---------------- 1: router (1 warp per token); writes fp16 x -------------
__global__ void router_kernel(const float* __restrict__ x, const float* __restrict__ Wg) {
    int t = (blockIdx.x * blockDim.x + threadIdx.x) >> 5;
    int lane = threadIdx.x & 31;
    if (t >= TT) return;
    const float* xr = x + (size_t)t * HH;
    __half* gx = g_X + (size_t)t * HH;
    float acc[EE];
#pragma unroll
    for (int e = 0; e < EE; e++) acc[e] = 0.f;
    for (int h = lane; h < HH; h += 32) {
        float xv = xr[h];
        gx[h] = __float2half_rn(xv);
        const float4* wg = reinterpret_cast<const float4*>(Wg + h * EE);
        float4 w0 = wg[0], w1 = wg[1];
        acc[0] += xv * w0.x; acc[1] += xv * w0.y; acc[2] += xv * w0.z; acc[3] += xv * w0.w;
        acc[4] += xv * w1.x; acc[5] += xv * w1.y; acc[6] += xv * w1.z; acc[7] += xv * w1.w;
    }
#pragma unroll
    for (int off = 16; off > 0; off >>= 1) {
#pragma unroll
        for (int e = 0; e < EE; e++)
            acc[e] += __shfl_xor_sync(0xffffffffu, acc[e], off);
    }
    if (lane == 0) {
        float m = acc[0];
#pragma unroll
        for (int e = 1; e < EE; e++) m = fmaxf(m, acc[e]);
        float p[EE];
        float s = 0.f;
#pragma unroll
        for (int e = 0; e < EE; e++) { p[e] = __expf(acc[e] - m); s += p[e]; }
        float inv = 1.f / s;
        int i0 = 0;
#pragma unroll
        for (int e = 1; e < EE; e++) if (p[e] > p[i0]) i0 = e;
        int i1 = -1;
#pragma unroll
        for (int e = 0; e < EE; e++) {
            if (e == i0) continue;
            if (i1 < 0 || p[e] > p[i1]) i1 = e;
        }
        float s0 = p[i0] * inv, s1 = p[i1] * inv;
        float denom = s0 + s1 + 1e-8f;
        float w0 = s0 / denom, w1 = s1 / denom;
        int pos0 = atomicAdd(&g_cnt[i0], 1);
        g_rows[i0 * TT + pos0] = t * 2 + 0;
        g_wts[i0 * TT + pos0] = w0;
        int pos1 = atomicAdd(&g_cnt[i1], 1);
        g_rows[i1 * TT + pos1] = t * 2 + 1;
        g_wts[i1 * TT + pos1] = w1;
    }
}

// smem sizing (halves)
#define G1_A_H   (64 * RS)
#define G1_B_H   (128 * RS)
#define G1_SMEM_B  ((NSTAGE * (G1_A_H + 2 * G1_B_H)) * 2)   // 102400 B
#define G2_A_H   (128 * RS)
#define G2_B_H   (128 * RS)
#define G2_SMEM_B  ((NSTAGE * (G2_A_H + G2_B_H)) * 2)       // 81920 B

// ---------------- 2: grouped GEMM1: F = SiLU(X@W11) * (X@W12) -------------
// fp16 m16n8k16 + ldmatrix fragments. 256 threads. BM=64, BN=128, BK=32.
// Warps 2(m)x4(n); warp tile 32x32 dual accum. 4-stage cp.async, lead-2.
// grid: (II/128, TT/64, EE)
__global__ __launch_bounds__(256, 2) void gemm1_kernel()
{
    extern __shared__ __half dynh[];
    int e = blockIdx.z;
    int cnt = g_cnt[e];
    int m0 = blockIdx.y * 64;
    if (m0 >= cnt) return;
    int n0 = blockIdx.x * 128;

    __half* AsB  = dynh;                          // [NSTAGE][64][RS]
    __half* B1sB = dynh + NSTAGE * G1_A_H;        // [NSTAGE][128][RS]
    __half* B2sB = B1sB + NSTAGE * G1_B_H;        // [NSTAGE][128][RS]
    __shared__ int rloc[64];

    int tid = threadIdx.x;
    int lane = tid & 31;
    int warp = tid >> 5;
    int gid = lane >> 2;
    int tig = lane & 3;
    int wm = (warp >> 2) * 32;
    int wn = (warp & 3) * 32;

    // ldmatrix.x4 lane->address components (halves)
    int a_lrow = (lane & 7) + ((lane >> 3) & 1) * 8;   // + wm + mt*16
    int a_lk   = (lane >> 4) * 8;                      // + ks*16
    int b_lrow = (lane & 7) + ((lane >> 4) & 1) * 8;   // + wn + np*16
    int b_lk   = ((lane >> 3) & 1) * 8;                // + ks*16

    if (tid < 64) {
        int mi = m0 + tid;
        if (mi >= cnt) mi = cnt - 1;
        rloc[tid] = g_rows[e * TT + mi];
    }
    __syncthreads();

    int a_row = tid >> 2, a_ch = (tid & 3) * 8;
    const __half* a_src = g_X + (size_t)(rloc[a_row] >> 1) * HH + a_ch;
    const __half* b1_src[2];
    const __half* b2_src[2];
    int b_soff[2];
#pragma unroll
    for (int p = 0; p < 2; p++) {
        int idx = tid + p * 256;
        int row = idx >> 2;
        int ch = (idx & 3) * 8;
        b1_src[p] = g_W11T + ((size_t)e * II + n0 + row) * HH + ch;
        b2_src[p] = g_W12T + ((size_t)e * II + n0 + row) * HH + ch;
        b_soff[p] = row * RS + ch;
    }
    int a_soff = a_row * RS + a_ch;

    float cG[2][4][4], cV[2][4][4];
#pragma unroll
    for (int a = 0; a < 2; a++)
#pragma unroll
        for (int b = 0; b < 4; b++)
#pragma unroll
            for (int c = 0; c < 4; c++) { cG[a][b][c] = 0.f; cV[a][b][c] = 0.f; }

    const int NIT = HH / 32;   // 32

#pragma unroll
    for (int pre = 0; pre < 2; pre++) {
        int kk = pre * 32;
        __half* As = AsB + pre * G1_A_H;
        __half* B1 = B1sB + pre * G1_B_H;
        __half* B2 = B2sB + pre * G1_B_H;
        cp16(As + a_soff, a_src + kk);
#pragma unroll
        for (int p = 0; p < 2; p++) {
            cp16(B1 + b_soff[p], b1_src[p] + kk);
            cp16(B2 + b_soff[p], b2_src[p] + kk);
        }
        CP_COMMIT();
    }

    int buf = 0;
    for (int it = 0; it < NIT; it++) {
        if (it + 2 < NIT) {
            int kk = (it + 2) * 32;
            int s = (it + 2) & (NSTAGE - 1);
            __half* As = AsB + s * G1_A_H;
            __half* B1 = B1sB + s * G1_B_H;
            __half* B2 = B2sB + s * G1_B_H;
            cp16(As + a_soff, a_src + kk);
#pragma unroll
            for (int p = 0; p < 2; p++) {
                cp16(B1 + b_soff[p], b1_src[p] + kk);
                cp16(B2 + b_soff[p], b2_src[p] + kk);
            }
        }
        CP_COMMIT();
        CP_WAIT2();
        __syncthreads();

        const __half* Abuf  = AsB + buf * G1_A_H;
        const __half* B1buf = B1sB + buf * G1_B_H;
        const __half* B2buf = B2sB + buf * G1_B_H;

#pragma unroll
        for (int ks = 0; ks < 2; ks++) {
            unsigned a[2][4];
#pragma unroll
            for (int mt = 0; mt < 2; mt++)
                ldsm4(a[mt], Abuf + (wm + mt * 16 + a_lrow) * RS + ks * 16 + a_lk);
#pragma unroll
            for (int np = 0; np < 2; np++) {
                unsigned b1[4], b2[4];
                ldsm4(b1, B1buf + (wn + np * 16 + b_lrow) * RS + ks * 16 + b_lk);
                ldsm4(b2, B2buf + (wn + np * 16 + b_lrow) * RS + ks * 16 + b_lk);
#pragma unroll
                for (int h = 0; h < 2; h++) {
                    unsigned bb1[2] = { b1[2 * h], b1[2 * h + 1] };
                    unsigned bb2[2] = { b2[2 * h], b2[2 * h + 1] };
#pragma unroll
                    for (int mt = 0; mt < 2; mt++) {
                        mma_f16(cG[mt][np * 2 + h], a[mt], bb1);
                        mma_f16(cV[mt][np * 2 + h], a[mt], bb2);
                    }
                }
            }
        }
        buf++; if (buf == NSTAGE) buf = 0;
    }

    // epilogue: f = g * sigmoid(g) * v -> g_F[r] (fp16)
#pragma unroll
    for (int mt = 0; mt < 2; mt++) {
#pragma unroll
        for (int half = 0; half < 2; half++) {
            int r = wm + mt * 16 + gid + half * 8;
            if (m0 + r < cnt) {
                int rg = rloc[r];
                __half* dst = g_F + (size_t)rg * II + n0 + wn;
#pragma unroll
                for (int nt = 0; nt < 4; nt++) {
                    float g0 = cG[mt][nt][half * 2 + 0], g1 = cG[mt][nt][half * 2 + 1];
                    float v0 = cV[mt][nt][half * 2 + 0], v1 = cV[mt][nt][half * 2 + 1];
                    float f0 = g0 * v0 / (1.f + __expf(-g0));
                    float f1 = g1 * v1 / (1.f + __expf(-g1));
                    *reinterpret_cast<__half2*>(dst + nt * 8 + tig * 2) =
                        __floats2half2_rn(f0, f1);
                }
            }
        }
    }
}

// ---------------- 3: grouped GEMM2: out += w[r] * (F[r] @ W2[e]) ----------
// fp16 m16n8k16 + ldmatrix. 256 threads. BM=128, BN=128, BK=32.
// Warps 2(m)x4(n); warp tile 64x32. RED epilogue into out.
// grid: (HH/128, TT/128, EE)
__global__ __launch_bounds__(256, 2) void gemm2_kernel(float* __restrict__ out)
{
    extern __shared__ __half dynh[];
    int e = blockIdx.z;
    int cnt = g_cnt[e];
    int m0 = blockIdx.y * 128;
    if (m0 >= cnt) return;
    int n0 = blockIdx.x * 128;

    __half* AsB = dynh;                           // [NSTAGE][128][RS]
    __half* BsB = dynh + NSTAGE * G2_A_H;         // [NSTAGE][128][RS]
    __shared__ int rloc[128];
    __shared__ float wloc[128];

    int tid = threadIdx.x;
    int lane = tid & 31;
    int warp = tid >> 5;
    int gid = lane >> 2;
    int tig = lane & 3;
    int wm = (warp >> 2) * 64;
    int wn = (warp & 3) * 32;

    int a_lrow = (lane & 7) + ((lane >> 3) & 1) * 8;
    int a_lk   = (lane >> 4) * 8;
    int b_lrow = (lane & 7) + ((lane >> 4) & 1) * 8;
    int b_lk   = ((lane >> 3) & 1) * 8;

    if (tid < 128) {
        int mi = m0 + tid;
        if (mi >= cnt) mi = cnt - 1;
        rloc[tid] = g_rows[e * TT + mi];
        wloc[tid] = g_wts[e * TT + mi];
    }
    __syncthreads();

    const __half* a_src[2];
    const __half* b_src[2];
    int soff[2];
#pragma unroll
    for (int p = 0; p < 2; p++) {
        int idx = tid + p * 256;
        int row = idx >> 2;
        int ch = (idx & 3) * 8;
        a_src[p] = g_F + (size_t)rloc[row] * II + ch;
        b_src[p] = g_W2T + ((size_t)e * HH + n0 + row) * II + ch;
        soff[p] = row * RS + ch;
    }

    float c[4][4][4];
#pragma unroll
    for (int a = 0; a < 4; a++)
#pragma unroll
        for (int b = 0; b < 4; b++)
#pragma unroll
            for (int cc = 0; cc < 4; cc++) c[a][b][cc] = 0.f;

    const int NIT = II / 32;   // 64

#pragma unroll
    for (int pre = 0; pre < 2; pre++) {
        int kk = pre * 32;
        __half* As = AsB + pre * G2_A_H;
        __half* Bs = BsB + pre * G2_B_H;
#pragma unroll
        for (int p = 0; p < 2; p++) {
            cp16(As + soff[p], a_src[p] + kk);
            cp16(Bs + soff[p], b_src[p] + kk);
        }
        CP_COMMIT();
    }

    int buf = 0;
    for (int it = 0; it < NIT; it++) {
        if (it + 2 < NIT) {
            int kk = (it + 2) * 32;
            int s = (it + 2) & (NSTAGE - 1);
            __half* As = AsB + s * G2_A_H;
            __half* Bs = BsB + s * G2_B_H;
#pragma unroll
            for (int p = 0; p < 2; p++) {
                cp16(As + soff[p], a_src[p] + kk);
                cp16(Bs + soff[p], b_src[p] + kk);
            }
        }
        CP_COMMIT();
        CP_WAIT2();
        __syncthreads();

        const __half* Abuf = AsB + buf * G2_A_H;
        const __half* Bbuf = BsB + buf * G2_B_H;

#pragma unroll
        for (int ks = 0; ks < 2; ks++) {
            unsigned a[4][4];
#pragma unroll
            for (int mt = 0; mt < 4; mt++)
                ldsm4(a[mt], Abuf + (wm + mt * 16 + a_lrow) * RS + ks * 16 + a_lk);
#pragma unroll
            for (int np = 0; np < 2; np++) {
                unsigned b[4];
                ldsm4(b, Bbuf + (wn + np * 16 + b_lrow) * RS + ks * 16 + b_lk);
#pragma unroll
                for (int h = 0; h < 2; h++) {
                    unsigned bb[2] = { b[2 * h], b[2 * h + 1] };
#pragma unroll
                    for (int mt = 0; mt < 4; mt++)
                        mma_f16(c[mt][np * 2 + h], a[mt], bb);
                }
            }
        }
        buf++; if (buf == NSTAGE) buf = 0;
    }

    // epilogue: scale by routing weight, RED into out[token]
#pragma unroll
    for (int mt = 0; mt < 4; mt++) {
#pragma unroll
        for (int half = 0; half < 2; half++) {
            int r = wm + mt * 16 + gid + half * 8;
            if (m0 + r < cnt) {
                int tok = rloc[r] >> 1;
                float wr = wloc[r];
                float* dst = out + (size_t)tok * HH + n0 + wn;
#pragma unroll
                for (int nt = 0; nt < 4; nt++) {
                    red_add_f32(dst + nt * 8 + tig * 2 + 0, wr * c[mt][nt][half * 2 + 0]);
                    red_add_f32(dst + nt * 8 + tig * 2 + 1, wr * c[mt][nt][half * 2 + 1]);
                }
            }
        }
    }
}

// ---------------- launch ----------------
extern "C" void kernel_launch(void* const* d_in, const int* in_sizes, int n_in,
                              void* d_out, int out_size) {
    (void)in_sizes; (void)n_in; (void)out_size;
    const float* x   = (const float*)d_in[0];
    const float* Wg  = (const float*)d_in[1];
    const float* W11 = (const float*)d_in[2];
    const float* W12 = (const float*)d_in[3];
    const float* W2  = (const float*)d_in[4];
    float* out = (float*)d_out;

    cudaFuncSetAttribute(gemm1_kernel, cudaFuncAttributeMaxDynamicSharedMemorySize, G1_SMEM_B);
    cudaFuncSetAttribute(gemm2_kernel, cudaFuncAttributeMaxDynamicSharedMemorySize, G2_SMEM_B);

    zero_cnt_kernel<<<1, 32>>>();
    zero_out_kernel<<<(TT * HH / 4 + 255) / 256, 256>>>(out);

    convert_w_kernel<<<dim3(II / 32, HH / 32, 3 * EE), dim3(32, 8)>>>(W11, W12, W2);

    router_kernel<<<TT / 4, 128>>>(x, Wg);

    dim3 g1(II / 128, TT / 64, EE);                        // (16, 64, 8)
    gemm1_kernel<<<g1, 256, G1_SMEM_B>>>();

    dim3 g2(HH / 128, TT / 128, EE);                       // (8, 32, 8)
    gemm2_kernel<<<g2, 256, G2_SMEM_B>>>(out);
}